// round 5
// baseline (speedup 1.0000x reference)
#include <cuda_runtime.h>
#include <math.h>

// Problem dims
constexpr int NB = 8, NT = 256, NU = 64, ND = 512, NH = 1024;
constexpr int PS_ROWS = NB * NT;              // 2048 rows of Ps
constexpr int PT_ROWS = NB * NU;              // 512 rows of Pt
constexpr int P_ROWS  = PS_ROWS + PT_ROWS;    // 2560
constexpr int M2      = NB * NT * NU;         // 131072 output rows
constexpr long MAIN_OUT = (long)M2 * ND;      // 67,108,864

// Scratch: Ps rows [0,2048), Pt rows [2048,2560), each NH wide. 10 MB.
__device__ float g_P[(size_t)P_ROWS * NH];

// ---------------------------------------------------------------------------
// Stage 1: P = concat(S, Tgt) @ W1  (+ b1 on the Tgt rows only)
//   M = 2560, N = 1024, K = 512.  128x128x8 double-buffered SGEMM.
// ---------------------------------------------------------------------------
__global__ __launch_bounds__(256) void stage1_kernel(
    const float* __restrict__ src, const float* __restrict__ tgt,
    const float* __restrict__ W1,  const float* __restrict__ b1)
{
    __shared__ float As[2][8][128];   // transposed: As[k][m]
    __shared__ float Bs[2][8][128];

    const int tid = threadIdx.x;
    const int tx = tid & 15, ty = tid >> 4;
    const int bx = blockIdx.x, by = blockIdx.y;

    const int  mBase = by * 128;
    const bool isTgt = (mBase >= PS_ROWS);

    // A loader: each thread loads float4 of one row
    const int mLoc = tid >> 1;
    const int kOff = (tid & 1) * 4;
    const float* aRow = isTgt ? (tgt + (size_t)(mBase - PS_ROWS + mLoc) * ND)
                              : (src + (size_t)(mBase + mLoc) * ND);

    // B loader: 8 rows x 128 cols, float4 per thread
    const int bK = tid >> 5;          // 0..7
    const int bN = (tid & 31) * 4;    // 0..124
    const float* bPtr = W1 + (size_t)bK * NH + bx * 128 + bN;

    float acc[8][8];
    #pragma unroll
    for (int i = 0; i < 8; ++i)
        #pragma unroll
        for (int j = 0; j < 8; ++j) acc[i][j] = 0.f;

    // Preload tile 0
    {
        float4 a4 = *(const float4*)(aRow + kOff);
        float4 b4 = *(const float4*)(bPtr);
        As[0][kOff + 0][mLoc] = a4.x;
        As[0][kOff + 1][mLoc] = a4.y;
        As[0][kOff + 2][mLoc] = a4.z;
        As[0][kOff + 3][mLoc] = a4.w;
        *(float4*)&Bs[0][bK][bN] = b4;
    }
    __syncthreads();

    const int KT = ND / 8;   // 64
    for (int kt = 0; kt < KT; ++kt) {
        const int buf = kt & 1;
        float4 aNx, bNx;
        if (kt + 1 < KT) {
            aNx = *(const float4*)(aRow + (kt + 1) * 8 + kOff);
            bNx = *(const float4*)(bPtr + (size_t)(kt + 1) * 8 * NH);
        }
        #pragma unroll
        for (int kk = 0; kk < 8; ++kk) {
            float4 a0 = *(const float4*)&As[buf][kk][ty * 8];
            float4 a1 = *(const float4*)&As[buf][kk][ty * 8 + 4];
            float4 b0 = *(const float4*)&Bs[buf][kk][tx * 8];
            float4 b1v = *(const float4*)&Bs[buf][kk][tx * 8 + 4];
            float a[8] = {a0.x, a0.y, a0.z, a0.w, a1.x, a1.y, a1.z, a1.w};
            float b[8] = {b0.x, b0.y, b0.z, b0.w, b1v.x, b1v.y, b1v.z, b1v.w};
            #pragma unroll
            for (int i = 0; i < 8; ++i)
                #pragma unroll
                for (int j = 0; j < 8; ++j)
                    acc[i][j] = fmaf(a[i], b[j], acc[i][j]);
        }
        if (kt + 1 < KT) {
            const int nb = buf ^ 1;
            As[nb][kOff + 0][mLoc] = aNx.x;
            As[nb][kOff + 1][mLoc] = aNx.y;
            As[nb][kOff + 2][mLoc] = aNx.z;
            As[nb][kOff + 3][mLoc] = aNx.w;
            *(float4*)&Bs[nb][bK][bN] = bNx;
        }
        __syncthreads();
    }

    // Epilogue: write to g_P; add b1 only for Tgt rows
    float bias[8];
    #pragma unroll
    for (int j = 0; j < 8; ++j)
        bias[j] = isTgt ? b1[bx * 128 + tx * 8 + j] : 0.f;

    #pragma unroll
    for (int i = 0; i < 8; ++i) {
        const int row = mBase + ty * 8 + i;
        float* gp = g_P + (size_t)row * NH + bx * 128 + tx * 8;
        float4 v0 = make_float4(acc[i][0] + bias[0], acc[i][1] + bias[1],
                                acc[i][2] + bias[2], acc[i][3] + bias[3]);
        float4 v1 = make_float4(acc[i][4] + bias[4], acc[i][5] + bias[5],
                                acc[i][6] + bias[6], acc[i][7] + bias[7]);
        *(float4*)(gp)     = v0;
        *(float4*)(gp + 4) = v1;
    }
}

// ---------------------------------------------------------------------------
// Stage 2: out = tanh(Ps[b,t] + Pt[b,u]) @ W2 + b2
//   M = 131072, N = 512, K = 1024.  A generated on the fly (2 loads + tanh).
// ---------------------------------------------------------------------------
__global__ __launch_bounds__(256) void stage2_kernel(
    const float* __restrict__ W2, const float* __restrict__ b2,
    float* __restrict__ out)
{
    __shared__ float As[2][8][128];
    __shared__ float Bs[2][8][128];

    const int tid = threadIdx.x;
    const int tx = tid & 15, ty = tid >> 4;
    const int bx = blockIdx.x, by = blockIdx.y;

    const int mBase = by * 128;

    // A generator: decode (b, t, u) for this thread's row
    const int mLoc = tid >> 1;
    const int kOff = (tid & 1) * 4;
    const int mG = mBase + mLoc;
    const int bb = mG >> 14;            // / (T*U)
    const int tt = (mG >> 6) & (NT - 1);
    const int uu = mG & (NU - 1);
    const float* psRow = g_P + (size_t)(bb * NT + tt) * NH;
    const float* ptRow = g_P + (size_t)(PS_ROWS + bb * NU + uu) * NH;

    // B loader
    const int bK = tid >> 5;
    const int bN = (tid & 31) * 4;
    const float* bPtr = W2 + (size_t)bK * ND + bx * 128 + bN;

    float acc[8][8];
    #pragma unroll
    for (int i = 0; i < 8; ++i)
        #pragma unroll
        for (int j = 0; j < 8; ++j) acc[i][j] = 0.f;

    // Preload tile 0
    {
        float4 p = *(const float4*)(psRow + kOff);
        float4 q = *(const float4*)(ptRow + kOff);
        As[0][kOff + 0][mLoc] = tanhf(p.x + q.x);
        As[0][kOff + 1][mLoc] = tanhf(p.y + q.y);
        As[0][kOff + 2][mLoc] = tanhf(p.z + q.z);
        As[0][kOff + 3][mLoc] = tanhf(p.w + q.w);
        *(float4*)&Bs[0][bK][bN] = *(const float4*)(bPtr);
    }
    __syncthreads();

    const int KT = NH / 8;   // 128
    for (int kt = 0; kt < KT; ++kt) {
        const int buf = kt & 1;
        float4 pNx, qNx, bNx;
        if (kt + 1 < KT) {
            pNx = *(const float4*)(psRow + (kt + 1) * 8 + kOff);
            qNx = *(const float4*)(ptRow + (kt + 1) * 8 + kOff);
            bNx = *(const float4*)(bPtr + (size_t)(kt + 1) * 8 * ND);
        }
        #pragma unroll
        for (int kk = 0; kk < 8; ++kk) {
            float4 a0 = *(const float4*)&As[buf][kk][ty * 8];
            float4 a1 = *(const float4*)&As[buf][kk][ty * 8 + 4];
            float4 b0 = *(const float4*)&Bs[buf][kk][tx * 8];
            float4 b1v = *(const float4*)&Bs[buf][kk][tx * 8 + 4];
            float a[8] = {a0.x, a0.y, a0.z, a0.w, a1.x, a1.y, a1.z, a1.w};
            float b[8] = {b0.x, b0.y, b0.z, b0.w, b1v.x, b1v.y, b1v.z, b1v.w};
            #pragma unroll
            for (int i = 0; i < 8; ++i)
                #pragma unroll
                for (int j = 0; j < 8; ++j)
                    acc[i][j] = fmaf(a[i], b[j], acc[i][j]);
        }
        if (kt + 1 < KT) {
            const int nb = buf ^ 1;
            As[nb][kOff + 0][mLoc] = tanhf(pNx.x + qNx.x);
            As[nb][kOff + 1][mLoc] = tanhf(pNx.y + qNx.y);
            As[nb][kOff + 2][mLoc] = tanhf(pNx.z + qNx.z);
            As[nb][kOff + 3][mLoc] = tanhf(pNx.w + qNx.w);
            *(float4*)&Bs[nb][bK][bN] = bNx;
        }
        __syncthreads();
    }

    // Epilogue: + b2, write to out
    float bias[8];
    #pragma unroll
    for (int j = 0; j < 8; ++j)
        bias[j] = b2[bx * 128 + tx * 8 + j];

    #pragma unroll
    for (int i = 0; i < 8; ++i) {
        const size_t row = (size_t)(mBase + ty * 8 + i);
        float* gp = out + row * ND + bx * 128 + tx * 8;
        float4 v0 = make_float4(acc[i][0] + bias[0], acc[i][1] + bias[1],
                                acc[i][2] + bias[2], acc[i][3] + bias[3]);
        float4 v1 = make_float4(acc[i][4] + bias[4], acc[i][5] + bias[5],
                                acc[i][6] + bias[6], acc[i][7] + bias[7]);
        *(float4*)(gp)     = v0;
        *(float4*)(gp + 4) = v1;
    }
}

// ---------------------------------------------------------------------------
// Pass-through of the length tensors (cast to output dtype), if the output
// buffer includes slots for them.
// ---------------------------------------------------------------------------
__global__ void tail_kernel(const int* __restrict__ sl, const int* __restrict__ tl,
                            float* __restrict__ out)
{
    const int i = threadIdx.x;
    if (i < NB)           out[MAIN_OUT + i]      = (float)sl[i];
    else if (i < 2 * NB)  out[MAIN_OUT + i]      = (float)tl[i - NB];
}

extern "C" void kernel_launch(void* const* d_in, const int* in_sizes, int n_in,
                              void* d_out, int out_size)
{
    const float* src  = (const float*)d_in[0];
    const int*   slen = (const int*)  d_in[1];
    const float* tgt  = (const float*)d_in[2];
    const int*   tlen = (const int*)  d_in[3];
    const float* W1   = (const float*)d_in[4];
    const float* b1   = (const float*)d_in[5];
    const float* W2   = (const float*)d_in[6];
    const float* b2   = (const float*)d_in[7];
    float* out = (float*)d_out;

    // Stage 1: P = [S; Tgt] @ W1 (+ b1 on Tgt rows). M=2560, N=1024, K=512.
    stage1_kernel<<<dim3(NH / 128, P_ROWS / 128), 256>>>(src, tgt, W1, b1);

    // Stage 2: out = tanh(Ps + Pt) @ W2 + b2. M=131072, N=512, K=1024.
    stage2_kernel<<<dim3(ND / 128, M2 / 128), 256>>>(W2, b2, out);

    // Length pass-through if the output buffer has room for them.
    if ((long)out_size >= MAIN_OUT + 2 * NB)
        tail_kernel<<<1, 32>>>(slen, tlen, out);
}

// round 7
// speedup vs baseline: 2.1649x; 2.1649x over previous
#include <cuda_runtime.h>
#include <cuda_bf16.h>
#include <math.h>
#include <stdint.h>

// Problem dims
constexpr int NB = 8, NT = 256, NU = 64, ND = 512, NH = 1024;
constexpr int PS_ROWS = NB * NT;              // 2048
constexpr int PT_ROWS = NB * NU;              // 512
constexpr int P_ROWS  = PS_ROWS + PT_ROWS;    // 2560
constexpr int M2      = NB * NT * NU;         // 131072
constexpr long MAIN_OUT = (long)M2 * ND;      // 67,108,864

// Scratch
__device__ float         g_P[(size_t)P_ROWS * NH];   // 10 MB
__device__ __nv_bfloat16 g_W2hi[(size_t)ND * NH];    // W2^T [n][k], bf16 hi
__device__ __nv_bfloat16 g_W2lo[(size_t)ND * NH];    // bf16 lo residual

// ===========================================================================
// Helpers (plain PTX, supported on compute_100 / sm_100)
// ===========================================================================
__device__ __forceinline__ uint32_t smem_u32(const void* p) {
    uint32_t a;
    asm("{ .reg .u64 t; cvta.to.shared.u64 t, %1; cvt.u32.u64 %0, t; }" : "=r"(a) : "l"(p));
    return a;
}

#define LDSM_X4(r, addr) \
    asm volatile("ldmatrix.sync.aligned.m8n8.x4.shared.b16 {%0,%1,%2,%3}, [%4];" \
        : "=r"((r)[0]), "=r"((r)[1]), "=r"((r)[2]), "=r"((r)[3]) : "r"(addr))

__device__ __forceinline__ void mma16816(float* d, const uint32_t* a,
                                         uint32_t b0, uint32_t b1) {
    asm volatile(
        "mma.sync.aligned.m16n8k16.row.col.f32.bf16.bf16.f32 "
        "{%0,%1,%2,%3}, {%4,%5,%6,%7}, {%8,%9}, {%0,%1,%2,%3};"
        : "+f"(d[0]), "+f"(d[1]), "+f"(d[2]), "+f"(d[3])
        : "r"(a[0]), "r"(a[1]), "r"(a[2]), "r"(a[3]), "r"(b0), "r"(b1));
}

// Fast tanh: abs error ~1e-6, saturates correctly at +-1 (inf-safe).
__device__ __forceinline__ float fast_tanh(float x) {
    float e = __expf(2.0f * x);
    return 1.0f - __fdividef(2.0f, e + 1.0f);
}

// ===========================================================================
// Stage 1: P = concat(S, Tgt) @ W1 (+ b1 on Tgt rows). Unchanged (122us, passing).
// ===========================================================================
__global__ __launch_bounds__(256) void stage1_kernel(
    const float* __restrict__ src, const float* __restrict__ tgt,
    const float* __restrict__ W1,  const float* __restrict__ b1)
{
    __shared__ float As[2][8][128];
    __shared__ float Bs[2][8][128];

    const int tid = threadIdx.x;
    const int tx = tid & 15, ty = tid >> 4;
    const int bx = blockIdx.x, by = blockIdx.y;

    const int  mBase = by * 128;
    const bool isTgt = (mBase >= PS_ROWS);

    const int mLoc = tid >> 1;
    const int kOff = (tid & 1) * 4;
    const float* aRow = isTgt ? (tgt + (size_t)(mBase - PS_ROWS + mLoc) * ND)
                              : (src + (size_t)(mBase + mLoc) * ND);

    const int bK = tid >> 5;
    const int bN = (tid & 31) * 4;
    const float* bPtr = W1 + (size_t)bK * NH + bx * 128 + bN;

    float acc[8][8];
    #pragma unroll
    for (int i = 0; i < 8; ++i)
        #pragma unroll
        for (int j = 0; j < 8; ++j) acc[i][j] = 0.f;

    {
        float4 a4 = *(const float4*)(aRow + kOff);
        float4 b4 = *(const float4*)(bPtr);
        As[0][kOff + 0][mLoc] = a4.x; As[0][kOff + 1][mLoc] = a4.y;
        As[0][kOff + 2][mLoc] = a4.z; As[0][kOff + 3][mLoc] = a4.w;
        *(float4*)&Bs[0][bK][bN] = b4;
    }
    __syncthreads();

    const int KT = ND / 8;
    for (int kt = 0; kt < KT; ++kt) {
        const int buf = kt & 1;
        float4 aNx, bNx;
        if (kt + 1 < KT) {
            aNx = *(const float4*)(aRow + (kt + 1) * 8 + kOff);
            bNx = *(const float4*)(bPtr + (size_t)(kt + 1) * 8 * NH);
        }
        #pragma unroll
        for (int kk = 0; kk < 8; ++kk) {
            float4 a0 = *(const float4*)&As[buf][kk][ty * 8];
            float4 a1 = *(const float4*)&As[buf][kk][ty * 8 + 4];
            float4 b0 = *(const float4*)&Bs[buf][kk][tx * 8];
            float4 b1v = *(const float4*)&Bs[buf][kk][tx * 8 + 4];
            float a[8] = {a0.x, a0.y, a0.z, a0.w, a1.x, a1.y, a1.z, a1.w};
            float b[8] = {b0.x, b0.y, b0.z, b0.w, b1v.x, b1v.y, b1v.z, b1v.w};
            #pragma unroll
            for (int i = 0; i < 8; ++i)
                #pragma unroll
                for (int j = 0; j < 8; ++j)
                    acc[i][j] = fmaf(a[i], b[j], acc[i][j]);
        }
        if (kt + 1 < KT) {
            const int nb = buf ^ 1;
            As[nb][kOff + 0][mLoc] = aNx.x; As[nb][kOff + 1][mLoc] = aNx.y;
            As[nb][kOff + 2][mLoc] = aNx.z; As[nb][kOff + 3][mLoc] = aNx.w;
            *(float4*)&Bs[nb][bK][bN] = bNx;
        }
        __syncthreads();
    }

    float bias[8];
    #pragma unroll
    for (int j = 0; j < 8; ++j)
        bias[j] = isTgt ? b1[bx * 128 + tx * 8 + j] : 0.f;

    #pragma unroll
    for (int i = 0; i < 8; ++i) {
        const int row = mBase + ty * 8 + i;
        float* gp = g_P + (size_t)row * NH + bx * 128 + tx * 8;
        float4 v0 = make_float4(acc[i][0] + bias[0], acc[i][1] + bias[1],
                                acc[i][2] + bias[2], acc[i][3] + bias[3]);
        float4 v1 = make_float4(acc[i][4] + bias[4], acc[i][5] + bias[5],
                                acc[i][6] + bias[6], acc[i][7] + bias[7]);
        *(float4*)(gp)     = v0;
        *(float4*)(gp + 4) = v1;
    }
}

// ===========================================================================
// W2 split preconvert: g_W2hi/lo[n][k] = hi/lo(W2[k][n])
// ===========================================================================
__global__ __launch_bounds__(256) void w2conv_kernel(const float* __restrict__ W2)
{
    int i = blockIdx.x * 256 + threadIdx.x;   // [n][k]
    int n = i >> 10;
    int k = i & (NH - 1);
    float v = W2[(size_t)k * ND + n];
    __nv_bfloat16 h = __float2bfloat16(v);
    g_W2hi[i] = h;
    g_W2lo[i] = __float2bfloat16(v - __bfloat162float(h));
}

// ===========================================================================
// Stage 2 (mma.sync bf16, 3-product split):
//   out = tanh(Ps[b,t]+Pt[b,u]) @ W2 + b2
//   CTA 128x128, 8 warps (4m x 2n), warp tile 32x64, k-chunk = 32 fp32.
//   SMEM rows padded to 80B -> conflict-free ldmatrix, no swizzle.
// ===========================================================================
constexpr int RS = 80;                       // bytes per 32-bf16 row (padded)
constexpr int KCH = 32;                      // fp32 k per chunk
constexpr int NCHUNKS = NH / KCH;            // 32

__global__ void __launch_bounds__(256, 2) stage2_mma_kernel(
    const float* __restrict__ b2, float* __restrict__ out)
{
    __shared__ __align__(16) unsigned char sA[2][128 * RS];  // [hi, lo]
    __shared__ __align__(16) unsigned char sB[2][128 * RS];  // [hi, lo]

    const int tid  = threadIdx.x;
    const int lane = tid & 31, wid = tid >> 5;
    const int warpM = wid >> 1;              // 0..3
    const int warpN = wid & 1;               // 0..1
    const int nBase = blockIdx.x * 128;
    const int mBase = blockIdx.y * 128;

    // --- generator / loader mapping: row = tid>>1, k-half = (tid&1)*16 ---
    const int gr = tid >> 1;
    const int gk = (tid & 1) * 16;
    const int mG = mBase + gr;
    const int bb = mG >> 14;
    const int tt = (mG >> 6) & (NT - 1);
    const int uu = mG & (NU - 1);
    const float* ps = g_P + (size_t)(bb * NT + tt) * NH + gk;
    const float* pt = g_P + (size_t)(PS_ROWS + bb * NU + uu) * NH + gk;
    unsigned char* aHiD = &sA[0][gr * RS + gk * 2];
    unsigned char* aLoD = &sA[1][gr * RS + gk * 2];

    const __nv_bfloat16* bhS = g_W2hi + (size_t)(nBase + gr) * NH + gk;
    const __nv_bfloat16* blS = g_W2lo + (size_t)(nBase + gr) * NH + gk;
    unsigned char* bHiD = &sB[0][gr * RS + gk * 2];
    unsigned char* bLoD = &sB[1][gr * RS + gk * 2];

    // --- ldmatrix lane byte-offsets ---
    const int sel = lane >> 3, l7 = lane & 7;
    // A (m16xk16 tiles): m0 r0-7 b0 | m1 r8-15 b0 | m2 r0-7 b16 | m3 r8-15 b16
    const uint32_t aOff = (uint32_t)((warpM * 32 + (sel & 1) * 8 + l7) * RS + (sel >> 1) * 16);
    // B (n16xk16 groups): m0 n0-7 b0 | m1 n0-7 b16 | m2 n8-15 b0 | m3 n8-15 b16
    const uint32_t bOff = (uint32_t)((warpN * 64 + ((sel >> 1) & 1) * 8 + l7) * RS + (sel & 1) * 16);

    const uint32_t sA0 = smem_u32(sA[0]), sA1 = smem_u32(sA[1]);
    const uint32_t sB0 = smem_u32(sB[0]), sB1 = smem_u32(sB[1]);

    float acc[2][8][4];
    #pragma unroll
    for (int mt = 0; mt < 2; ++mt)
        #pragma unroll
        for (int nt = 0; nt < 8; ++nt)
            #pragma unroll
            for (int j = 0; j < 4; ++j) acc[mt][nt][j] = 0.f;

    for (int c = 0; c < NCHUNKS; ++c) {
        if (c) __syncthreads();              // buffer reuse
        const int k0 = c * KCH;

        // ---- A: tanh(ps+pt) -> bf16 hi/lo (16 values/thread) ----
        {
            const float* p = ps + k0;
            const float* q = pt + k0;
            uint32_t hw[8], lw[8];
            #pragma unroll
            for (int g = 0; g < 4; ++g) {
                float4 p4 = *(const float4*)(p + g * 4);
                float4 q4 = *(const float4*)(q + g * 4);
                float x0 = fast_tanh(p4.x + q4.x);
                float x1 = fast_tanh(p4.y + q4.y);
                float x2 = fast_tanh(p4.z + q4.z);
                float x3 = fast_tanh(p4.w + q4.w);
                __nv_bfloat162 h0 = __floats2bfloat162_rn(x0, x1);
                __nv_bfloat162 h1 = __floats2bfloat162_rn(x2, x3);
                hw[g * 2 + 0] = *(uint32_t*)&h0;
                hw[g * 2 + 1] = *(uint32_t*)&h1;
                __nv_bfloat162 l0 = __floats2bfloat162_rn(
                    x0 - __bfloat162float(h0.x), x1 - __bfloat162float(h0.y));
                __nv_bfloat162 l1 = __floats2bfloat162_rn(
                    x2 - __bfloat162float(h1.x), x3 - __bfloat162float(h1.y));
                lw[g * 2 + 0] = *(uint32_t*)&l0;
                lw[g * 2 + 1] = *(uint32_t*)&l1;
            }
            *(uint4*)(aHiD)      = make_uint4(hw[0], hw[1], hw[2], hw[3]);
            *(uint4*)(aHiD + 16) = make_uint4(hw[4], hw[5], hw[6], hw[7]);
            *(uint4*)(aLoD)      = make_uint4(lw[0], lw[1], lw[2], lw[3]);
            *(uint4*)(aLoD + 16) = make_uint4(lw[4], lw[5], lw[6], lw[7]);
        }

        // ---- B: copy preconverted hi/lo (16 bf16/thread each) ----
        {
            uint4 h0 = *(const uint4*)(bhS + k0);
            uint4 h1 = *(const uint4*)(bhS + k0 + 8);
            uint4 l0 = *(const uint4*)(blS + k0);
            uint4 l1 = *(const uint4*)(blS + k0 + 8);
            *(uint4*)(bHiD)      = h0;
            *(uint4*)(bHiD + 16) = h1;
            *(uint4*)(bLoD)      = l0;
            *(uint4*)(bLoD + 16) = l1;
        }

        __syncthreads();

        // ---- 3 passes: (Ah,Bh), (Ah,Bl), (Al,Bh) ----
        #pragma unroll
        for (int pass = 0; pass < 3; ++pass) {
            const uint32_t aBase = (pass == 2 ? sA1 : sA0) + aOff;
            const uint32_t bBase = (pass == 1 ? sB1 : sB0) + bOff;
            #pragma unroll
            for (int ks = 0; ks < 2; ++ks) {
                uint32_t a[2][4];
                LDSM_X4(a[0], aBase + ks * 32);
                LDSM_X4(a[1], aBase + 16 * RS + ks * 32);
                uint32_t bf[4][4];
                #pragma unroll
                for (int g = 0; g < 4; ++g)
                    LDSM_X4(bf[g], bBase + g * 16 * RS + ks * 32);
                #pragma unroll
                for (int mt = 0; mt < 2; ++mt)
                    #pragma unroll
                    for (int nt = 0; nt < 8; ++nt)
                        mma16816(acc[mt][nt], a[mt],
                                 bf[nt >> 1][(nt & 1) * 2 + 0],
                                 bf[nt >> 1][(nt & 1) * 2 + 1]);
            }
        }
    }

    // ---- Epilogue: + b2, direct stores ----
    const int colOff = (lane & 3) * 2;
    const int rowOff = lane >> 2;
    #pragma unroll
    for (int mt = 0; mt < 2; ++mt) {
        const int r0 = mBase + warpM * 32 + mt * 16 + rowOff;
        float* row0 = out + (size_t)r0 * ND + nBase + warpN * 64 + colOff;
        float* row1 = row0 + (size_t)8 * ND;
        #pragma unroll
        for (int nt = 0; nt < 8; ++nt) {
            const float bx = __ldg(b2 + nBase + warpN * 64 + nt * 8 + colOff);
            const float by = __ldg(b2 + nBase + warpN * 64 + nt * 8 + colOff + 1);
            float2 v0 = make_float2(acc[mt][nt][0] + bx, acc[mt][nt][1] + by);
            float2 v1 = make_float2(acc[mt][nt][2] + bx, acc[mt][nt][3] + by);
            *(float2*)(row0 + nt * 8) = v0;
            *(float2*)(row1 + nt * 8) = v1;
        }
    }
}

// ---------------------------------------------------------------------------
// Length pass-through tail
// ---------------------------------------------------------------------------
__global__ void tail_kernel(const int* __restrict__ sl, const int* __restrict__ tl,
                            float* __restrict__ out)
{
    const int i = threadIdx.x;
    if (i < NB)           out[MAIN_OUT + i] = (float)sl[i];
    else if (i < 2 * NB)  out[MAIN_OUT + i] = (float)tl[i - NB];
}

extern "C" void kernel_launch(void* const* d_in, const int* in_sizes, int n_in,
                              void* d_out, int out_size)
{
    const float* src  = (const float*)d_in[0];
    const int*   slen = (const int*)  d_in[1];
    const float* tgt  = (const float*)d_in[2];
    const int*   tlen = (const int*)  d_in[3];
    const float* W1   = (const float*)d_in[4];
    const float* b1   = (const float*)d_in[5];
    const float* W2   = (const float*)d_in[6];
    const float* b2   = (const float*)d_in[7];
    float* out = (float*)d_out;

    // Stage 1: P = [S; Tgt] @ W1 (+ b1 on Tgt rows)
    stage1_kernel<<<dim3(NH / 128, P_ROWS / 128), 256>>>(src, tgt, W1, b1);

    // W2 split preconvert (independent of stage 1)
    w2conv_kernel<<<(ND * NH) / 256, 256>>>(W2);

    // Stage 2: mma.sync split-bf16 GEMM with fused tanh A-generation
    stage2_mma_kernel<<<dim3(ND / 128, M2 / 128), 256>>>(b2, out);

    // Length pass-through if the output buffer has room
    if ((long)out_size >= MAIN_OUT + 2 * NB)
        tail_kernel<<<1, 32>>>(slen, tlen, out);
}

// round 9
// speedup vs baseline: 2.6281x; 1.2139x over previous
#include <cuda_runtime.h>
#include <cuda_fp16.h>
#include <math.h>
#include <stdint.h>

// Problem dims
constexpr int NB = 8, NT = 256, NU = 64, ND = 512, NH = 1024;
constexpr int PS_ROWS = NB * NT;              // 2048
constexpr int PT_ROWS = NB * NU;              // 512
constexpr int P_ROWS  = PS_ROWS + PT_ROWS;    // 2560
constexpr int M2      = NB * NT * NU;         // 131072
constexpr long MAIN_OUT = (long)M2 * ND;      // 67,108,864

// Scratch
__device__ float  g_P[(size_t)P_ROWS * NH];   // 10 MB
__device__ __half g_W2hi[(size_t)ND * NH];    // W2^T [n][k], fp16 hi
__device__ __half g_W2lo[(size_t)ND * NH];    // fp16 lo residual

// ===========================================================================
// Helpers (plain PTX, compute_100-safe)
// ===========================================================================
__device__ __forceinline__ uint32_t smem_u32(const void* p) {
    uint32_t a;
    asm("{ .reg .u64 t; cvta.to.shared.u64 t, %1; cvt.u32.u64 %0, t; }" : "=r"(a) : "l"(p));
    return a;
}

#define LDSM_X4(r, addr) \
    asm volatile("ldmatrix.sync.aligned.m8n8.x4.shared.b16 {%0,%1,%2,%3}, [%4];" \
        : "=r"((r)[0]), "=r"((r)[1]), "=r"((r)[2]), "=r"((r)[3]) : "r"(addr))

__device__ __forceinline__ void mma16816(float* d, const uint32_t* a,
                                         uint32_t b0, uint32_t b1) {
    asm volatile(
        "mma.sync.aligned.m16n8k16.row.col.f32.f16.f16.f32 "
        "{%0,%1,%2,%3}, {%4,%5,%6,%7}, {%8,%9}, {%0,%1,%2,%3};"
        : "+f"(d[0]), "+f"(d[1]), "+f"(d[2]), "+f"(d[3])
        : "r"(a[0]), "r"(a[1]), "r"(a[2]), "r"(a[3]), "r"(b0), "r"(b1));
}

// Fast tanh: abs error ~1e-6, saturates correctly at +-1 (inf-safe).
__device__ __forceinline__ float fast_tanh(float x) {
    float e = __expf(2.0f * x);
    return 1.0f - __fdividef(2.0f, e + 1.0f);
}

// ===========================================================================
// Stage 1: P = concat(S, Tgt) @ W1 (+ b1 on Tgt rows). Unchanged (122us).
// ===========================================================================
__global__ __launch_bounds__(256) void stage1_kernel(
    const float* __restrict__ src, const float* __restrict__ tgt,
    const float* __restrict__ W1,  const float* __restrict__ b1)
{
    __shared__ float As[2][8][128];
    __shared__ float Bs[2][8][128];

    const int tid = threadIdx.x;
    const int tx = tid & 15, ty = tid >> 4;
    const int bx = blockIdx.x, by = blockIdx.y;

    const int  mBase = by * 128;
    const bool isTgt = (mBase >= PS_ROWS);

    const int mLoc = tid >> 1;
    const int kOff = (tid & 1) * 4;
    const float* aRow = isTgt ? (tgt + (size_t)(mBase - PS_ROWS + mLoc) * ND)
                              : (src + (size_t)(mBase + mLoc) * ND);

    const int bK = tid >> 5;
    const int bN = (tid & 31) * 4;
    const float* bPtr = W1 + (size_t)bK * NH + bx * 128 + bN;

    float acc[8][8];
    #pragma unroll
    for (int i = 0; i < 8; ++i)
        #pragma unroll
        for (int j = 0; j < 8; ++j) acc[i][j] = 0.f;

    {
        float4 a4 = *(const float4*)(aRow + kOff);
        float4 b4 = *(const float4*)(bPtr);
        As[0][kOff + 0][mLoc] = a4.x; As[0][kOff + 1][mLoc] = a4.y;
        As[0][kOff + 2][mLoc] = a4.z; As[0][kOff + 3][mLoc] = a4.w;
        *(float4*)&Bs[0][bK][bN] = b4;
    }
    __syncthreads();

    const int KT = ND / 8;
    for (int kt = 0; kt < KT; ++kt) {
        const int buf = kt & 1;
        float4 aNx, bNx;
        if (kt + 1 < KT) {
            aNx = *(const float4*)(aRow + (kt + 1) * 8 + kOff);
            bNx = *(const float4*)(bPtr + (size_t)(kt + 1) * 8 * NH);
        }
        #pragma unroll
        for (int kk = 0; kk < 8; ++kk) {
            float4 a0 = *(const float4*)&As[buf][kk][ty * 8];
            float4 a1 = *(const float4*)&As[buf][kk][ty * 8 + 4];
            float4 b0 = *(const float4*)&Bs[buf][kk][tx * 8];
            float4 b1v = *(const float4*)&Bs[buf][kk][tx * 8 + 4];
            float a[8] = {a0.x, a0.y, a0.z, a0.w, a1.x, a1.y, a1.z, a1.w};
            float b[8] = {b0.x, b0.y, b0.z, b0.w, b1v.x, b1v.y, b1v.z, b1v.w};
            #pragma unroll
            for (int i = 0; i < 8; ++i)
                #pragma unroll
                for (int j = 0; j < 8; ++j)
                    acc[i][j] = fmaf(a[i], b[j], acc[i][j]);
        }
        if (kt + 1 < KT) {
            const int nb = buf ^ 1;
            As[nb][kOff + 0][mLoc] = aNx.x; As[nb][kOff + 1][mLoc] = aNx.y;
            As[nb][kOff + 2][mLoc] = aNx.z; As[nb][kOff + 3][mLoc] = aNx.w;
            *(float4*)&Bs[nb][bK][bN] = bNx;
        }
        __syncthreads();
    }

    float bias[8];
    #pragma unroll
    for (int j = 0; j < 8; ++j)
        bias[j] = isTgt ? b1[bx * 128 + tx * 8 + j] : 0.f;

    #pragma unroll
    for (int i = 0; i < 8; ++i) {
        const int row = mBase + ty * 8 + i;
        float* gp = g_P + (size_t)row * NH + bx * 128 + tx * 8;
        float4 v0 = make_float4(acc[i][0] + bias[0], acc[i][1] + bias[1],
                                acc[i][2] + bias[2], acc[i][3] + bias[3]);
        float4 v1 = make_float4(acc[i][4] + bias[4], acc[i][5] + bias[5],
                                acc[i][6] + bias[6], acc[i][7] + bias[7]);
        *(float4*)(gp)     = v0;
        *(float4*)(gp + 4) = v1;
    }
}

// ===========================================================================
// W2 split preconvert: g_W2hi/lo[n][k] = fp16 hi/lo of W2[k][n]
// ===========================================================================
__global__ __launch_bounds__(256) void w2conv_kernel(const float* __restrict__ W2)
{
    int i = blockIdx.x * 256 + threadIdx.x;   // [n][k]
    int n = i >> 10;
    int k = i & (NH - 1);
    float v = W2[(size_t)k * ND + n];
    __half h = __float2half_rn(v);
    g_W2hi[i] = h;
    g_W2lo[i] = __float2half_rn(v - __half2float(h));
}

// ===========================================================================
// Stage 2 (mma.sync fp16, 2-product split, software-pipelined):
//   out = tanh(Ps[b,t]+Pt[b,u]) @ W2 + b2
//   D = Ah*Bh + Ah*Bl   (A single fp16, B fp16 hi/lo; dropped Al*B ~ 2^-12)
//   CTA 128x128, 8 warps (4m x 2n), k-chunk = 32, double-buffered dyn smem.
// ===========================================================================
constexpr int RS  = 80;                       // bytes per 32-fp16 row (padded)
constexpr int KCH = 32;
constexpr int NCHUNKS = NH / KCH;             // 32
constexpr int TILE_B  = 128 * RS;             // 10240 bytes per tile
constexpr int BUFSZ   = 3 * TILE_B;           // A, Bh, Bl
constexpr int SMEM2   = 2 * BUFSZ;            // 61440

__global__ void __launch_bounds__(256, 2) stage2_mma_kernel(
    const float* __restrict__ b2, float* __restrict__ out)
{
    extern __shared__ __align__(16) unsigned char dynsm[];

    const int tid  = threadIdx.x;
    const int lane = tid & 31, wid = tid >> 5;
    const int warpM = wid >> 1;               // 0..3
    const int warpN = wid & 1;                // 0..1
    const int nBase = blockIdx.x * 128;
    const int mBase = blockIdx.y * 128;

    // generator / loader mapping: row = tid>>1, k-half = (tid&1)*16
    const int gr = tid >> 1;
    const int gk = (tid & 1) * 16;
    const int mG = mBase + gr;
    const int bb = mG >> 14;
    const int tt = (mG >> 6) & (NT - 1);
    const int uu = mG & (NU - 1);
    const float* ps = g_P + (size_t)(bb * NT + tt) * NH + gk;
    const float* pt = g_P + (size_t)(PS_ROWS + bb * NU + uu) * NH + gk;
    const __half* bhS = g_W2hi + (size_t)(nBase + gr) * NH + gk;
    const __half* blS = g_W2lo + (size_t)(nBase + gr) * NH + gk;

    // ldmatrix lane byte-offsets (identical mapping to the R7-validated code)
    const int sel = lane >> 3, l7 = lane & 7;
    const uint32_t aOff = (uint32_t)((warpM * 32 + (sel & 1) * 8 + l7) * RS + (sel >> 1) * 16);
    const uint32_t bOff = (uint32_t)((warpN * 64 + ((sel >> 1) & 1) * 8 + l7) * RS + (sel & 1) * 16);
    const uint32_t sbase = smem_u32(dynsm);

    float acc[2][8][4];
    #pragma unroll
    for (int mt = 0; mt < 2; ++mt)
        #pragma unroll
        for (int nt = 0; nt < 8; ++nt)
            #pragma unroll
            for (int j = 0; j < 4; ++j) acc[mt][nt][j] = 0.f;

    // Generate chunk c into buffer buf: A=tanh->fp16, B=copy hi/lo fp16.
    auto gen = [&](int c, int buf) {
        unsigned char* bp = dynsm + buf * BUFSZ;
        const float* p = ps + c * KCH;
        const float* q = pt + c * KCH;
        uint32_t hw[8];
        #pragma unroll
        for (int g = 0; g < 4; ++g) {
            float4 p4 = *(const float4*)(p + g * 4);
            float4 q4 = *(const float4*)(q + g * 4);
            float x0 = fast_tanh(p4.x + q4.x);
            float x1 = fast_tanh(p4.y + q4.y);
            float x2 = fast_tanh(p4.z + q4.z);
            float x3 = fast_tanh(p4.w + q4.w);
            __half2 h0 = __floats2half2_rn(x0, x1);
            __half2 h1 = __floats2half2_rn(x2, x3);
            hw[g * 2 + 0] = *(uint32_t*)&h0;
            hw[g * 2 + 1] = *(uint32_t*)&h1;
        }
        unsigned char* aD = bp + gr * RS + gk * 2;
        *(uint4*)(aD)      = make_uint4(hw[0], hw[1], hw[2], hw[3]);
        *(uint4*)(aD + 16) = make_uint4(hw[4], hw[5], hw[6], hw[7]);

        uint4 h0 = *(const uint4*)(bhS + c * KCH);
        uint4 h1 = *(const uint4*)(bhS + c * KCH + 8);
        uint4 l0 = *(const uint4*)(blS + c * KCH);
        uint4 l1 = *(const uint4*)(blS + c * KCH + 8);
        unsigned char* bhD = bp + TILE_B + gr * RS + gk * 2;
        unsigned char* blD = bp + 2 * TILE_B + gr * RS + gk * 2;
        *(uint4*)(bhD)      = h0;
        *(uint4*)(bhD + 16) = h1;
        *(uint4*)(blD)      = l0;
        *(uint4*)(blD + 16) = l1;
    };

    gen(0, 0);
    __syncthreads();

    for (int c = 0; c < NCHUNKS; ++c) {
        const int buf = c & 1;
        const uint32_t base = sbase + buf * BUFSZ;
        const uint32_t aB = base + aOff;

        // A fragments (shared across both B passes)
        uint32_t a[2][2][4];                  // [ks][mt]
        #pragma unroll
        for (int ks = 0; ks < 2; ++ks) {
            LDSM_X4(a[ks][0], aB + ks * 32);
            LDSM_X4(a[ks][1], aB + 16 * RS + ks * 32);
        }

        // Two passes: Bh then Bl
        #pragma unroll
        for (int pass = 0; pass < 2; ++pass) {
            const uint32_t bB = base + (1 + pass) * TILE_B + bOff;
            #pragma unroll
            for (int ks = 0; ks < 2; ++ks) {
                uint32_t bf[4][4];
                #pragma unroll
                for (int g = 0; g < 4; ++g)
                    LDSM_X4(bf[g], bB + g * 16 * RS + ks * 32);
                #pragma unroll
                for (int mt = 0; mt < 2; ++mt)
                    #pragma unroll
                    for (int nt = 0; nt < 8; ++nt)
                        mma16816(acc[mt][nt], a[ks][mt],
                                 bf[nt >> 1][(nt & 1) * 2 + 0],
                                 bf[nt >> 1][(nt & 1) * 2 + 1]);
            }
        }

        // Overlap: generate next chunk into the other buffer while the
        // tensor pipe drains this chunk's MMAs.
        if (c + 1 < NCHUNKS) gen(c + 1, buf ^ 1);
        __syncthreads();
    }

    // Epilogue: + b2, direct stores
    const int colOff = (lane & 3) * 2;
    const int rowOff = lane >> 2;
    #pragma unroll
    for (int mt = 0; mt < 2; ++mt) {
        const int r0 = mBase + warpM * 32 + mt * 16 + rowOff;
        float* row0 = out + (size_t)r0 * ND + nBase + warpN * 64 + colOff;
        float* row1 = row0 + (size_t)8 * ND;
        #pragma unroll
        for (int nt = 0; nt < 8; ++nt) {
            const float bx = __ldg(b2 + nBase + warpN * 64 + nt * 8 + colOff);
            const float by = __ldg(b2 + nBase + warpN * 64 + nt * 8 + colOff + 1);
            float2 v0 = make_float2(acc[mt][nt][0] + bx, acc[mt][nt][1] + by);
            float2 v1 = make_float2(acc[mt][nt][2] + bx, acc[mt][nt][3] + by);
            *(float2*)(row0 + nt * 8) = v0;
            *(float2*)(row1 + nt * 8) = v1;
        }
    }
}

// ---------------------------------------------------------------------------
// Length pass-through tail
// ---------------------------------------------------------------------------
__global__ void tail_kernel(const int* __restrict__ sl, const int* __restrict__ tl,
                            float* __restrict__ out)
{
    const int i = threadIdx.x;
    if (i < NB)           out[MAIN_OUT + i] = (float)sl[i];
    else if (i < 2 * NB)  out[MAIN_OUT + i] = (float)tl[i - NB];
}

extern "C" void kernel_launch(void* const* d_in, const int* in_sizes, int n_in,
                              void* d_out, int out_size)
{
    const float* src  = (const float*)d_in[0];
    const int*   slen = (const int*)  d_in[1];
    const float* tgt  = (const float*)d_in[2];
    const int*   tlen = (const int*)  d_in[3];
    const float* W1   = (const float*)d_in[4];
    const float* b1   = (const float*)d_in[5];
    const float* W2   = (const float*)d_in[6];
    const float* b2   = (const float*)d_in[7];
    float* out = (float*)d_out;

    // Opt-in to >48KB dynamic smem (idempotent, capture-safe).
    cudaFuncSetAttribute(stage2_mma_kernel,
                         cudaFuncAttributeMaxDynamicSharedMemorySize, SMEM2);

    // Stage 1: P = [S; Tgt] @ W1 (+ b1 on Tgt rows)
    stage1_kernel<<<dim3(NH / 128, P_ROWS / 128), 256>>>(src, tgt, W1, b1);

    // W2 fp16 hi/lo preconvert (independent of stage 1)
    w2conv_kernel<<<(ND * NH) / 256, 256>>>(W2);

    // Stage 2: pipelined mma.sync fp16 2-product GEMM with fused tanh
    stage2_mma_kernel<<<dim3(ND / 128, M2 / 128), 256, SMEM2>>>(b2, out);

    // Length pass-through if the output buffer has room
    if ((long)out_size >= MAIN_OUT + 2 * NB)
        tail_kernel<<<1, 32>>>(slen, tlen, out);
}

// round 10
// speedup vs baseline: 4.8300x; 1.8378x over previous
#include <cuda_runtime.h>
#include <cuda_fp16.h>
#include <math.h>
#include <stdint.h>

// Problem dims
constexpr int NB = 8, NT = 256, NU = 64, ND = 512, NH = 1024;
constexpr int PS_ROWS = NB * NT;              // 2048
constexpr int PT_ROWS = NB * NU;              // 512
constexpr int P_ROWS  = PS_ROWS + PT_ROWS;    // 2560
constexpr int M2      = NB * NT * NU;         // 131072
constexpr long MAIN_OUT = (long)M2 * ND;      // 67,108,864

// Scratch
__device__ float  g_P[(size_t)P_ROWS * NH];   // 10 MB
__device__ __half g_W2h[(size_t)ND * NH];     // W2^T [n][k], fp16 (1 MB)
__device__ __half g_H[(size_t)M2 * NH];       // H = fp16(tanh(Ps+Pt)), 268 MB

// ===========================================================================
// Helpers (plain PTX, compute_100-safe)
// ===========================================================================
__device__ __forceinline__ uint32_t smem_u32(const void* p) {
    uint32_t a;
    asm("{ .reg .u64 t; cvta.to.shared.u64 t, %1; cvt.u32.u64 %0, t; }" : "=r"(a) : "l"(p));
    return a;
}

#define LDSM_X4(r, addr) \
    asm volatile("ldmatrix.sync.aligned.m8n8.x4.shared.b16 {%0,%1,%2,%3}, [%4];" \
        : "=r"((r)[0]), "=r"((r)[1]), "=r"((r)[2]), "=r"((r)[3]) : "r"(addr))

__device__ __forceinline__ void mma16816(float* d, const uint32_t* a,
                                         uint32_t b0, uint32_t b1) {
    asm volatile(
        "mma.sync.aligned.m16n8k16.row.col.f32.f16.f16.f32 "
        "{%0,%1,%2,%3}, {%4,%5,%6,%7}, {%8,%9}, {%0,%1,%2,%3};"
        : "+f"(d[0]), "+f"(d[1]), "+f"(d[2]), "+f"(d[3])
        : "r"(a[0]), "r"(a[1]), "r"(a[2]), "r"(a[3]), "r"(b0), "r"(b1));
}

__device__ __forceinline__ void cp_async16(uint32_t dst, const void* src) {
    asm volatile("cp.async.cg.shared.global [%0], [%1], 16;"
        :: "r"(dst), "l"(__cvta_generic_to_global(src)) : "memory");
}
#define CP_COMMIT()  asm volatile("cp.async.commit_group;" ::: "memory")
#define CP_WAIT(n)   asm volatile("cp.async.wait_group %0;" :: "n"(n) : "memory")

// Fast tanh: abs error ~1e-6, saturates correctly at +-1 (inf-safe).
__device__ __forceinline__ float fast_tanh(float x) {
    float e = __expf(2.0f * x);
    return 1.0f - __fdividef(2.0f, e + 1.0f);
}

// ===========================================================================
// Stage 1: P = concat(S, Tgt) @ W1 (+ b1 on Tgt rows). Unchanged (122us).
// ===========================================================================
__global__ __launch_bounds__(256) void stage1_kernel(
    const float* __restrict__ src, const float* __restrict__ tgt,
    const float* __restrict__ W1,  const float* __restrict__ b1)
{
    __shared__ float As[2][8][128];
    __shared__ float Bs[2][8][128];

    const int tid = threadIdx.x;
    const int tx = tid & 15, ty = tid >> 4;
    const int bx = blockIdx.x, by = blockIdx.y;

    const int  mBase = by * 128;
    const bool isTgt = (mBase >= PS_ROWS);

    const int mLoc = tid >> 1;
    const int kOff = (tid & 1) * 4;
    const float* aRow = isTgt ? (tgt + (size_t)(mBase - PS_ROWS + mLoc) * ND)
                              : (src + (size_t)(mBase + mLoc) * ND);

    const int bK = tid >> 5;
    const int bN = (tid & 31) * 4;
    const float* bPtr = W1 + (size_t)bK * NH + bx * 128 + bN;

    float acc[8][8];
    #pragma unroll
    for (int i = 0; i < 8; ++i)
        #pragma unroll
        for (int j = 0; j < 8; ++j) acc[i][j] = 0.f;

    {
        float4 a4 = *(const float4*)(aRow + kOff);
        float4 b4 = *(const float4*)(bPtr);
        As[0][kOff + 0][mLoc] = a4.x; As[0][kOff + 1][mLoc] = a4.y;
        As[0][kOff + 2][mLoc] = a4.z; As[0][kOff + 3][mLoc] = a4.w;
        *(float4*)&Bs[0][bK][bN] = b4;
    }
    __syncthreads();

    const int KT = ND / 8;
    for (int kt = 0; kt < KT; ++kt) {
        const int buf = kt & 1;
        float4 aNx, bNx;
        if (kt + 1 < KT) {
            aNx = *(const float4*)(aRow + (kt + 1) * 8 + kOff);
            bNx = *(const float4*)(bPtr + (size_t)(kt + 1) * 8 * NH);
        }
        #pragma unroll
        for (int kk = 0; kk < 8; ++kk) {
            float4 a0 = *(const float4*)&As[buf][kk][ty * 8];
            float4 a1 = *(const float4*)&As[buf][kk][ty * 8 + 4];
            float4 b0 = *(const float4*)&Bs[buf][kk][tx * 8];
            float4 b1v = *(const float4*)&Bs[buf][kk][tx * 8 + 4];
            float a[8] = {a0.x, a0.y, a0.z, a0.w, a1.x, a1.y, a1.z, a1.w};
            float b[8] = {b0.x, b0.y, b0.z, b0.w, b1v.x, b1v.y, b1v.z, b1v.w};
            #pragma unroll
            for (int i = 0; i < 8; ++i)
                #pragma unroll
                for (int j = 0; j < 8; ++j)
                    acc[i][j] = fmaf(a[i], b[j], acc[i][j]);
        }
        if (kt + 1 < KT) {
            const int nb = buf ^ 1;
            As[nb][kOff + 0][mLoc] = aNx.x; As[nb][kOff + 1][mLoc] = aNx.y;
            As[nb][kOff + 2][mLoc] = aNx.z; As[nb][kOff + 3][mLoc] = aNx.w;
            *(float4*)&Bs[nb][bK][bN] = bNx;
        }
        __syncthreads();
    }

    float bias[8];
    #pragma unroll
    for (int j = 0; j < 8; ++j)
        bias[j] = isTgt ? b1[bx * 128 + tx * 8 + j] : 0.f;

    #pragma unroll
    for (int i = 0; i < 8; ++i) {
        const int row = mBase + ty * 8 + i;
        float* gp = g_P + (size_t)row * NH + bx * 128 + tx * 8;
        float4 v0 = make_float4(acc[i][0] + bias[0], acc[i][1] + bias[1],
                                acc[i][2] + bias[2], acc[i][3] + bias[3]);
        float4 v1 = make_float4(acc[i][4] + bias[4], acc[i][5] + bias[5],
                                acc[i][6] + bias[6], acc[i][7] + bias[7]);
        *(float4*)(gp)     = v0;
        *(float4*)(gp + 4) = v1;
    }
}

// ===========================================================================
// W2 preconvert: g_W2h[n][k] = fp16(W2[k][n])
// ===========================================================================
__global__ __launch_bounds__(256) void w2conv_kernel(const float* __restrict__ W2)
{
    int i = blockIdx.x * 256 + threadIdx.x;   // [n][k]
    int n = i >> 10;
    int k = i & (NH - 1);
    g_W2h[i] = __float2half_rn(W2[(size_t)k * ND + n]);
}

// ===========================================================================
// Stage 1.5: H[m][k] = fp16(tanh(Ps[b,t][k] + Pt[b,u][k]))
//   One block per (b,t); iterates u. Ps row stays in registers.
// ===========================================================================
__global__ __launch_bounds__(128) void h_kernel()
{
    const int bt = blockIdx.x;                // b*NT + t
    const int b  = bt >> 8;
    const int k0 = threadIdx.x * 8;

    const float* ps = g_P + (size_t)bt * NH + k0;
    const float4 p0 = *(const float4*)(ps);
    const float4 p1 = *(const float4*)(ps + 4);

    const float* ptB = g_P + (size_t)(PS_ROWS + b * NU) * NH + k0;
    __half* hout = g_H + (size_t)bt * NU * NH + k0;

    for (int u = 0; u < NU; ++u) {
        const float* q = ptB + (size_t)u * NH;
        float4 q0 = *(const float4*)(q);
        float4 q1 = *(const float4*)(q + 4);
        __half2 h0 = __floats2half2_rn(fast_tanh(p0.x + q0.x), fast_tanh(p0.y + q0.y));
        __half2 h1 = __floats2half2_rn(fast_tanh(p0.z + q0.z), fast_tanh(p0.w + q0.w));
        __half2 h2 = __floats2half2_rn(fast_tanh(p1.x + q1.x), fast_tanh(p1.y + q1.y));
        __half2 h3 = __floats2half2_rn(fast_tanh(p1.z + q1.z), fast_tanh(p1.w + q1.w));
        uint4 v = make_uint4(*(uint32_t*)&h0, *(uint32_t*)&h1,
                             *(uint32_t*)&h2, *(uint32_t*)&h3);
        *(uint4*)(hout + (size_t)u * NH) = v;
    }
}

// ===========================================================================
// Stage 2: out = H @ W2^T + b2  — pure fp16 GEMM, cp.async 3-stage pipeline.
//   CTA 128x128, 8 warps (4m x 2n), k-chunk = 32, single fp16 product.
// ===========================================================================
constexpr int RS  = 80;                       // bytes per 32-fp16 row (padded)
constexpr int KCH = 32;
constexpr int NCHUNKS = NH / KCH;             // 32
constexpr int TILE_B  = 128 * RS;             // 10240 bytes per tile
constexpr int BUFSZ   = 2 * TILE_B;           // A, B
constexpr int NSTAGE  = 3;
constexpr int SMEM2   = NSTAGE * BUFSZ;       // 61440

__global__ void __launch_bounds__(256, 2) stage2_mma_kernel(
    const float* __restrict__ b2, float* __restrict__ out)
{
    extern __shared__ __align__(16) unsigned char dynsm[];

    const int tid  = threadIdx.x;
    const int lane = tid & 31, wid = tid >> 5;
    const int warpM = wid >> 1;               // 0..3
    const int warpN = wid & 1;                // 0..1
    const int nBase = blockIdx.x * 128;
    const int mBase = blockIdx.y * 128;

    // copy mapping: row = tid>>1, k-half = (tid&1)*16
    const int gr = tid >> 1;
    const int gk = (tid & 1) * 16;
    const __half* aS0 = g_H   + (size_t)(mBase + gr) * NH + gk;
    const __half* bS0 = g_W2h + (size_t)(nBase + gr) * NH + gk;
    const uint32_t dOffA = (uint32_t)(gr * RS + gk * 2);
    const uint32_t dOffB = (uint32_t)(TILE_B + gr * RS + gk * 2);

    // ldmatrix lane byte-offsets (R9-validated mapping)
    const int sel = lane >> 3, l7 = lane & 7;
    const uint32_t aOff = (uint32_t)((warpM * 32 + (sel & 1) * 8 + l7) * RS + (sel >> 1) * 16);
    const uint32_t bOff = (uint32_t)((warpN * 64 + ((sel >> 1) & 1) * 8 + l7) * RS + (sel & 1) * 16);
    const uint32_t sbase = smem_u32(dynsm);

    float acc[2][8][4];
    #pragma unroll
    for (int mt = 0; mt < 2; ++mt)
        #pragma unroll
        for (int nt = 0; nt < 8; ++nt)
            #pragma unroll
            for (int j = 0; j < 4; ++j) acc[mt][nt][j] = 0.f;

    auto issue_cp = [&](int c, int stage) {
        const uint32_t base = sbase + stage * BUFSZ;
        const __half* aS = aS0 + c * KCH;
        const __half* bS = bS0 + c * KCH;
        cp_async16(base + dOffA,      aS);
        cp_async16(base + dOffA + 16, aS + 8);
        cp_async16(base + dOffB,      bS);
        cp_async16(base + dOffB + 16, bS + 8);
        CP_COMMIT();
    };

    issue_cp(0, 0);
    issue_cp(1, 1);

    int rd = 0, wr = 2;
    for (int c = 0; c < NCHUNKS; ++c) {
        if (c == NCHUNKS - 1) { CP_WAIT(0); } else { CP_WAIT(1); }
        __syncthreads();

        const uint32_t base = sbase + rd * BUFSZ;
        const uint32_t aB = base + aOff;
        const uint32_t bB = base + TILE_B + bOff;

        #pragma unroll
        for (int ks = 0; ks < 2; ++ks) {
            uint32_t a[2][4];
            LDSM_X4(a[0], aB + ks * 32);
            LDSM_X4(a[1], aB + 16 * RS + ks * 32);
            uint32_t bf[4][4];
            #pragma unroll
            for (int g = 0; g < 4; ++g)
                LDSM_X4(bf[g], bB + g * 16 * RS + ks * 32);
            #pragma unroll
            for (int mt = 0; mt < 2; ++mt)
                #pragma unroll
                for (int nt = 0; nt < 8; ++nt)
                    mma16816(acc[mt][nt], a[mt],
                             bf[nt >> 1][(nt & 1) * 2 + 0],
                             bf[nt >> 1][(nt & 1) * 2 + 1]);
        }

        if (c + 2 < NCHUNKS) issue_cp(c + 2, wr);
        rd = (rd == 2) ? 0 : rd + 1;
        wr = (wr == 2) ? 0 : wr + 1;
    }

    // Epilogue: + b2, direct stores
    const int colOff = (lane & 3) * 2;
    const int rowOff = lane >> 2;
    #pragma unroll
    for (int mt = 0; mt < 2; ++mt) {
        const int r0 = mBase + warpM * 32 + mt * 16 + rowOff;
        float* row0 = out + (size_t)r0 * ND + nBase + warpN * 64 + colOff;
        float* row1 = row0 + (size_t)8 * ND;
        #pragma unroll
        for (int nt = 0; nt < 8; ++nt) {
            const float bx = __ldg(b2 + nBase + warpN * 64 + nt * 8 + colOff);
            const float by = __ldg(b2 + nBase + warpN * 64 + nt * 8 + colOff + 1);
            float2 v0 = make_float2(acc[mt][nt][0] + bx, acc[mt][nt][1] + by);
            float2 v1 = make_float2(acc[mt][nt][2] + bx, acc[mt][nt][3] + by);
            *(float2*)(row0 + nt * 8) = v0;
            *(float2*)(row1 + nt * 8) = v1;
        }
    }
}

// ---------------------------------------------------------------------------
// Length pass-through tail
// ---------------------------------------------------------------------------
__global__ void tail_kernel(const int* __restrict__ sl, const int* __restrict__ tl,
                            float* __restrict__ out)
{
    const int i = threadIdx.x;
    if (i < NB)           out[MAIN_OUT + i] = (float)sl[i];
    else if (i < 2 * NB)  out[MAIN_OUT + i] = (float)tl[i - NB];
}

extern "C" void kernel_launch(void* const* d_in, const int* in_sizes, int n_in,
                              void* d_out, int out_size)
{
    const float* src  = (const float*)d_in[0];
    const int*   slen = (const int*)  d_in[1];
    const float* tgt  = (const float*)d_in[2];
    const int*   tlen = (const int*)  d_in[3];
    const float* W1   = (const float*)d_in[4];
    const float* b1   = (const float*)d_in[5];
    const float* W2   = (const float*)d_in[6];
    const float* b2   = (const float*)d_in[7];
    float* out = (float*)d_out;

    // Opt-in to >48KB dynamic smem (idempotent, capture-safe).
    cudaFuncSetAttribute(stage2_mma_kernel,
                         cudaFuncAttributeMaxDynamicSharedMemorySize, SMEM2);

    // Stage 1: P = [S; Tgt] @ W1 (+ b1 on Tgt rows)
    stage1_kernel<<<dim3(NH / 128, P_ROWS / 128), 256>>>(src, tgt, W1, b1);

    // W2 fp16 preconvert (independent of stage 1)
    w2conv_kernel<<<(ND * NH) / 256, 256>>>(W2);

    // Stage 1.5: H = fp16(tanh(Ps + Pt)), computed once per element
    h_kernel<<<PS_ROWS, 128>>>();

    // Stage 2: cp.async-pipelined single-product fp16 GEMM
    stage2_mma_kernel<<<dim3(ND / 128, M2 / 128), 256, SMEM2>>>(b2, out);

    // Length pass-through if the output buffer has room
    if ((long)out_size >= MAIN_OUT + 2 * NB)
        tail_kernel<<<1, 32>>>(slen, tlen, out);
}

// round 11
// speedup vs baseline: 4.9005x; 1.0146x over previous
#include <cuda_runtime.h>
#include <cuda_fp16.h>
#include <math.h>
#include <stdint.h>

// Problem dims
constexpr int NB = 8, NT = 256, NU = 64, ND = 512, NH = 1024;
constexpr int PS_ROWS = NB * NT;              // 2048
constexpr int PT_ROWS = NB * NU;              // 512
constexpr int P_ROWS  = PS_ROWS + PT_ROWS;    // 2560
constexpr int M2      = NB * NT * NU;         // 131072
constexpr long MAIN_OUT = (long)M2 * ND;      // 67,108,864

// Scratch
__device__ float  g_P[(size_t)P_ROWS * NH];   // 10 MB
__device__ __half g_W1h[(size_t)NH * ND];     // W1^T [n][k] fp16 hi (n<1024, k<512)
__device__ __half g_W1l[(size_t)NH * ND];     // fp16 lo residual
__device__ __half g_W2h[(size_t)ND * NH];     // W2^T [n][k] fp16
__device__ __half g_H[(size_t)M2 * NH];       // H = fp16(tanh(Ps+Pt)), 268 MB

// ===========================================================================
// Helpers (plain PTX, compute_100-safe)
// ===========================================================================
__device__ __forceinline__ uint32_t smem_u32(const void* p) {
    uint32_t a;
    asm("{ .reg .u64 t; cvta.to.shared.u64 t, %1; cvt.u32.u64 %0, t; }" : "=r"(a) : "l"(p));
    return a;
}

#define LDSM_X4(r, addr) \
    asm volatile("ldmatrix.sync.aligned.m8n8.x4.shared.b16 {%0,%1,%2,%3}, [%4];" \
        : "=r"((r)[0]), "=r"((r)[1]), "=r"((r)[2]), "=r"((r)[3]) : "r"(addr))

__device__ __forceinline__ void mma16816(float* d, const uint32_t* a,
                                         uint32_t b0, uint32_t b1) {
    asm volatile(
        "mma.sync.aligned.m16n8k16.row.col.f32.f16.f16.f32 "
        "{%0,%1,%2,%3}, {%4,%5,%6,%7}, {%8,%9}, {%0,%1,%2,%3};"
        : "+f"(d[0]), "+f"(d[1]), "+f"(d[2]), "+f"(d[3])
        : "r"(a[0]), "r"(a[1]), "r"(a[2]), "r"(a[3]), "r"(b0), "r"(b1));
}

__device__ __forceinline__ void cp_async16(uint32_t dst, const void* src) {
    asm volatile("cp.async.cg.shared.global [%0], [%1], 16;"
        :: "r"(dst), "l"(__cvta_generic_to_global(src)) : "memory");
}
#define CP_COMMIT()  asm volatile("cp.async.commit_group;" ::: "memory")
#define CP_WAIT(n)   asm volatile("cp.async.wait_group %0;" :: "n"(n) : "memory")

// Fast tanh: abs error ~1e-6, saturates correctly at +-1 (inf-safe).
__device__ __forceinline__ float fast_tanh(float x) {
    float e = __expf(2.0f * x);
    return 1.0f - __fdividef(2.0f, e + 1.0f);
}

// ===========================================================================
// Weight preconverts
// ===========================================================================
__global__ __launch_bounds__(256) void w1conv_kernel(const float* __restrict__ W1)
{
    int i = blockIdx.x * 256 + threadIdx.x;   // [n][k], n<NH, k<ND
    int n = i >> 9;                           // /ND
    int k = i & (ND - 1);
    float v = W1[(size_t)k * NH + n];
    __half h = __float2half_rn(v);
    g_W1h[i] = h;
    g_W1l[i] = __float2half_rn(v - __half2float(h));
}

__global__ __launch_bounds__(256) void w2conv_kernel(const float* __restrict__ W2)
{
    int i = blockIdx.x * 256 + threadIdx.x;   // [n][k], n<ND, k<NH
    int n = i >> 10;
    int k = i & (NH - 1);
    g_W2h[i] = __float2half_rn(W2[(size_t)k * ND + n]);
}

// ===========================================================================
// Stage 1 (mma.sync, 3-product fp16 split): P = concat(S,Tgt) @ W1 (+b1 Tgt)
//   D = AhBh + AhBl + AlBh  (both operands split; error ~2^-22)
//   M = 2560, N = 1024, K = 512.  CTA 128x128, k-chunk 32, double-buffered.
// ===========================================================================
constexpr int RS1     = 80;                   // bytes per 32-fp16 row (padded)
constexpr int KCH1    = 32;
constexpr int NCH1    = ND / KCH1;            // 16
constexpr int TILE1   = 128 * RS1;            // 10240
constexpr int BUFSZ1  = 4 * TILE1;            // Ah, Al, Bh, Bl
constexpr int SMEM1   = 2 * BUFSZ1;           // 81920

__global__ void __launch_bounds__(256, 2) stage1_mma_kernel(
    const float* __restrict__ src, const float* __restrict__ tgt,
    const float* __restrict__ b1)
{
    extern __shared__ __align__(16) unsigned char dynsm[];

    const int tid  = threadIdx.x;
    const int lane = tid & 31, wid = tid >> 5;
    const int warpM = wid >> 1, warpN = wid & 1;
    const int nBase = blockIdx.x * 128;
    const int mBase = blockIdx.y * 128;
    const bool isTgt = (mBase >= PS_ROWS);

    const int gr = tid >> 1;
    const int gk = (tid & 1) * 16;
    const float* aRow = (isTgt ? tgt + (size_t)(mBase - PS_ROWS + gr) * ND
                               : src + (size_t)(mBase + gr) * ND) + gk;
    const __half* bhS = g_W1h + (size_t)(nBase + gr) * ND + gk;
    const __half* blS = g_W1l + (size_t)(nBase + gr) * ND + gk;

    const int sel = lane >> 3, l7 = lane & 7;
    const uint32_t aOff = (uint32_t)((warpM * 32 + (sel & 1) * 8 + l7) * RS1 + (sel >> 1) * 16);
    const uint32_t bOff = (uint32_t)((warpN * 64 + ((sel >> 1) & 1) * 8 + l7) * RS1 + (sel & 1) * 16);
    const uint32_t sbase = smem_u32(dynsm);

    float acc[2][8][4];
    #pragma unroll
    for (int mt = 0; mt < 2; ++mt)
        #pragma unroll
        for (int nt = 0; nt < 8; ++nt)
            #pragma unroll
            for (int j = 0; j < 4; ++j) acc[mt][nt][j] = 0.f;

    auto gen = [&](int c, int buf) {
        unsigned char* bp = dynsm + buf * BUFSZ1;
        const float* p = aRow + c * KCH1;
        uint32_t hw[8], lw[8];
        #pragma unroll
        for (int g = 0; g < 4; ++g) {
            float4 p4 = *(const float4*)(p + g * 4);
            __half hx = __float2half_rn(p4.x), hy = __float2half_rn(p4.y);
            __half hz = __float2half_rn(p4.z), hw4 = __float2half_rn(p4.w);
            __half2 h0; h0.x = hx; h0.y = hy;
            __half2 h1; h1.x = hz; h1.y = hw4;
            __half2 l0 = __floats2half2_rn(p4.x - __half2float(hx), p4.y - __half2float(hy));
            __half2 l1 = __floats2half2_rn(p4.z - __half2float(hz), p4.w - __half2float(hw4));
            hw[g * 2 + 0] = *(uint32_t*)&h0; hw[g * 2 + 1] = *(uint32_t*)&h1;
            lw[g * 2 + 0] = *(uint32_t*)&l0; lw[g * 2 + 1] = *(uint32_t*)&l1;
        }
        unsigned char* aH = bp + gr * RS1 + gk * 2;
        unsigned char* aL = aH + TILE1;
        *(uint4*)(aH)      = make_uint4(hw[0], hw[1], hw[2], hw[3]);
        *(uint4*)(aH + 16) = make_uint4(hw[4], hw[5], hw[6], hw[7]);
        *(uint4*)(aL)      = make_uint4(lw[0], lw[1], lw[2], lw[3]);
        *(uint4*)(aL + 16) = make_uint4(lw[4], lw[5], lw[6], lw[7]);

        uint4 h0 = *(const uint4*)(bhS + c * KCH1);
        uint4 h1 = *(const uint4*)(bhS + c * KCH1 + 8);
        uint4 l0 = *(const uint4*)(blS + c * KCH1);
        uint4 l1 = *(const uint4*)(blS + c * KCH1 + 8);
        unsigned char* bH = bp + 2 * TILE1 + gr * RS1 + gk * 2;
        unsigned char* bL = bH + TILE1;
        *(uint4*)(bH)      = h0; *(uint4*)(bH + 16) = h1;
        *(uint4*)(bL)      = l0; *(uint4*)(bL + 16) = l1;
    };

    gen(0, 0);
    __syncthreads();

    for (int c = 0; c < NCH1; ++c) {
        const int buf = c & 1;
        const uint32_t base = sbase + buf * BUFSZ1;

        uint32_t ah[2][2][4], al[2][2][4];       // [ks][mt]
        #pragma unroll
        for (int ks = 0; ks < 2; ++ks) {
            LDSM_X4(ah[ks][0], base + aOff + ks * 32);
            LDSM_X4(ah[ks][1], base + aOff + 16 * RS1 + ks * 32);
            LDSM_X4(al[ks][0], base + TILE1 + aOff + ks * 32);
            LDSM_X4(al[ks][1], base + TILE1 + aOff + 16 * RS1 + ks * 32);
        }
        #pragma unroll
        for (int pass = 0; pass < 3; ++pass) {
            const uint32_t bB = base + (pass == 1 ? 3 : 2) * TILE1 + bOff;
            #pragma unroll
            for (int ks = 0; ks < 2; ++ks) {
                uint32_t bf[4][4];
                #pragma unroll
                for (int g = 0; g < 4; ++g)
                    LDSM_X4(bf[g], bB + g * 16 * RS1 + ks * 32);
                #pragma unroll
                for (int mt = 0; mt < 2; ++mt)
                    #pragma unroll
                    for (int nt = 0; nt < 8; ++nt)
                        mma16816(acc[mt][nt],
                                 (pass == 2 ? al[ks][mt] : ah[ks][mt]),
                                 bf[nt >> 1][(nt & 1) * 2 + 0],
                                 bf[nt >> 1][(nt & 1) * 2 + 1]);
            }
        }
        if (c + 1 < NCH1) gen(c + 1, buf ^ 1);
        __syncthreads();
    }

    // Epilogue: (+ b1 on Tgt rows), write g_P
    const int colOff = (lane & 3) * 2;
    const int rowOff = lane >> 2;
    #pragma unroll
    for (int mt = 0; mt < 2; ++mt) {
        const int r0 = mBase + warpM * 32 + mt * 16 + rowOff;
        float* row0 = g_P + (size_t)r0 * NH + nBase + warpN * 64 + colOff;
        float* row1 = row0 + (size_t)8 * NH;
        #pragma unroll
        for (int nt = 0; nt < 8; ++nt) {
            const int col = nBase + warpN * 64 + nt * 8 + colOff;
            const float bx = isTgt ? __ldg(b1 + col)     : 0.f;
            const float by = isTgt ? __ldg(b1 + col + 1) : 0.f;
            *(float2*)(row0 + nt * 8) = make_float2(acc[mt][nt][0] + bx, acc[mt][nt][1] + by);
            *(float2*)(row1 + nt * 8) = make_float2(acc[mt][nt][2] + bx, acc[mt][nt][3] + by);
        }
    }
}

// ===========================================================================
// Stage 1.5: H[m][k] = fp16(tanh(Ps[b,t][k] + Pt[b,u][k]))
// ===========================================================================
__global__ __launch_bounds__(128) void h_kernel()
{
    const int bt = blockIdx.x;                // b*NT + t
    const int b  = bt >> 8;
    const int k0 = threadIdx.x * 8;

    const float* ps = g_P + (size_t)bt * NH + k0;
    const float4 p0 = *(const float4*)(ps);
    const float4 p1 = *(const float4*)(ps + 4);

    const float* ptB = g_P + (size_t)(PS_ROWS + b * NU) * NH + k0;
    __half* hout = g_H + (size_t)bt * NU * NH + k0;

    for (int u = 0; u < NU; ++u) {
        const float* q = ptB + (size_t)u * NH;
        float4 q0 = *(const float4*)(q);
        float4 q1 = *(const float4*)(q + 4);
        __half2 h0 = __floats2half2_rn(fast_tanh(p0.x + q0.x), fast_tanh(p0.y + q0.y));
        __half2 h1 = __floats2half2_rn(fast_tanh(p0.z + q0.z), fast_tanh(p0.w + q0.w));
        __half2 h2 = __floats2half2_rn(fast_tanh(p1.x + q1.x), fast_tanh(p1.y + q1.y));
        __half2 h3 = __floats2half2_rn(fast_tanh(p1.z + q1.z), fast_tanh(p1.w + q1.w));
        *(uint4*)(hout + (size_t)u * NH) =
            make_uint4(*(uint32_t*)&h0, *(uint32_t*)&h1, *(uint32_t*)&h2, *(uint32_t*)&h3);
    }
}

// ===========================================================================
// Stage 2: out = H @ W2^T + b2 — fp16 GEMM, k-chunk 64, 3-stage cp.async.
// ===========================================================================
constexpr int RS2  = 144;                     // bytes per 64-fp16 row (128 + 16 pad)
constexpr int KCH2 = 64;
constexpr int NCH2 = NH / KCH2;               // 16
constexpr int TILE2  = 128 * RS2;             // 18432
constexpr int BUFSZ2 = 2 * TILE2;             // A, B
constexpr int NSTAGE = 3;
constexpr int SMEM2  = NSTAGE * BUFSZ2;       // 110592

__global__ void __launch_bounds__(256, 2) stage2_mma_kernel(
    const float* __restrict__ b2, float* __restrict__ out)
{
    extern __shared__ __align__(16) unsigned char dynsm[];

    const int tid  = threadIdx.x;
    const int lane = tid & 31, wid = tid >> 5;
    const int warpM = wid >> 1, warpN = wid & 1;
    const int nBase = blockIdx.x * 128;
    const int mBase = blockIdx.y * 128;

    // copy mapping: row = tid>>1, 32-elem half = (tid&1)*32
    const int gr = tid >> 1;
    const int gk = (tid & 1) * 32;
    const __half* aS0 = g_H   + (size_t)(mBase + gr) * NH + gk;
    const __half* bS0 = g_W2h + (size_t)(nBase + gr) * NH + gk;
    const uint32_t dOffA = (uint32_t)(gr * RS2 + gk * 2);
    const uint32_t dOffB = (uint32_t)(TILE2 + gr * RS2 + gk * 2);

    const int sel = lane >> 3, l7 = lane & 7;
    const uint32_t aOff = (uint32_t)((warpM * 32 + (sel & 1) * 8 + l7) * RS2 + (sel >> 1) * 16);
    const uint32_t bOff = (uint32_t)((warpN * 64 + ((sel >> 1) & 1) * 8 + l7) * RS2 + (sel & 1) * 16);
    const uint32_t sbase = smem_u32(dynsm);

    float acc[2][8][4];
    #pragma unroll
    for (int mt = 0; mt < 2; ++mt)
        #pragma unroll
        for (int nt = 0; nt < 8; ++nt)
            #pragma unroll
            for (int j = 0; j < 4; ++j) acc[mt][nt][j] = 0.f;

    auto issue_cp = [&](int c, int stage) {
        const uint32_t base = sbase + stage * BUFSZ2;
        const __half* aS = aS0 + c * KCH2;
        const __half* bS = bS0 + c * KCH2;
        #pragma unroll
        for (int g = 0; g < 4; ++g) {
            cp_async16(base + dOffA + g * 16, aS + g * 8);
            cp_async16(base + dOffB + g * 16, bS + g * 8);
        }
        CP_COMMIT();
    };

    issue_cp(0, 0);
    issue_cp(1, 1);

    int rd = 0, wr = 2;
    for (int c = 0; c < NCH2; ++c) {
        if (c == NCH2 - 1) { CP_WAIT(0); } else { CP_WAIT(1); }
        __syncthreads();

        const uint32_t base = sbase + rd * BUFSZ2;
        const uint32_t aB = base + aOff;
        const uint32_t bB = base + TILE2 + bOff;

        #pragma unroll
        for (int ks = 0; ks < 4; ++ks) {
            uint32_t a[2][4];
            LDSM_X4(a[0], aB + ks * 32);
            LDSM_X4(a[1], aB + 16 * RS2 + ks * 32);
            uint32_t bf[4][4];
            #pragma unroll
            for (int g = 0; g < 4; ++g)
                LDSM_X4(bf[g], bB + g * 16 * RS2 + ks * 32);
            #pragma unroll
            for (int mt = 0; mt < 2; ++mt)
                #pragma unroll
                for (int nt = 0; nt < 8; ++nt)
                    mma16816(acc[mt][nt], a[mt],
                             bf[nt >> 1][(nt & 1) * 2 + 0],
                             bf[nt >> 1][(nt & 1) * 2 + 1]);
        }

        if (c + 2 < NCH2) issue_cp(c + 2, wr);
        rd = (rd == 2) ? 0 : rd + 1;
        wr = (wr == 2) ? 0 : wr + 1;
    }

    // Epilogue: + b2, direct stores
    const int colOff = (lane & 3) * 2;
    const int rowOff = lane >> 2;
    #pragma unroll
    for (int mt = 0; mt < 2; ++mt) {
        const int r0 = mBase + warpM * 32 + mt * 16 + rowOff;
        float* row0 = out + (size_t)r0 * ND + nBase + warpN * 64 + colOff;
        float* row1 = row0 + (size_t)8 * ND;
        #pragma unroll
        for (int nt = 0; nt < 8; ++nt) {
            const float bx = __ldg(b2 + nBase + warpN * 64 + nt * 8 + colOff);
            const float by = __ldg(b2 + nBase + warpN * 64 + nt * 8 + colOff + 1);
            *(float2*)(row0 + nt * 8) = make_float2(acc[mt][nt][0] + bx, acc[mt][nt][1] + by);
            *(float2*)(row1 + nt * 8) = make_float2(acc[mt][nt][2] + bx, acc[mt][nt][3] + by);
        }
    }
}

// ---------------------------------------------------------------------------
// Length pass-through tail
// ---------------------------------------------------------------------------
__global__ void tail_kernel(const int* __restrict__ sl, const int* __restrict__ tl,
                            float* __restrict__ out)
{
    const int i = threadIdx.x;
    if (i < NB)           out[MAIN_OUT + i] = (float)sl[i];
    else if (i < 2 * NB)  out[MAIN_OUT + i] = (float)tl[i - NB];
}

extern "C" void kernel_launch(void* const* d_in, const int* in_sizes, int n_in,
                              void* d_out, int out_size)
{
    const float* src  = (const float*)d_in[0];
    const int*   slen = (const int*)  d_in[1];
    const float* tgt  = (const float*)d_in[2];
    const int*   tlen = (const int*)  d_in[3];
    const float* W1   = (const float*)d_in[4];
    const float* b1   = (const float*)d_in[5];
    const float* W2   = (const float*)d_in[6];
    const float* b2   = (const float*)d_in[7];
    float* out = (float*)d_out;

    // Opt-in to >48KB dynamic smem (host-side, capture-safe).
    cudaFuncSetAttribute(stage1_mma_kernel,
                         cudaFuncAttributeMaxDynamicSharedMemorySize, SMEM1);
    cudaFuncSetAttribute(stage2_mma_kernel,
                         cudaFuncAttributeMaxDynamicSharedMemorySize, SMEM2);

    // Weight preconverts (independent)
    w1conv_kernel<<<(NH * ND) / 256, 256>>>(W1);
    w2conv_kernel<<<(ND * NH) / 256, 256>>>(W2);

    // Stage 1: P = [S; Tgt] @ W1 (+ b1 on Tgt rows), 3-product fp16 mma
    stage1_mma_kernel<<<dim3(NH / 128, P_ROWS / 128), 256, SMEM1>>>(src, tgt, b1);

    // Stage 1.5: H = fp16(tanh(Ps + Pt))
    h_kernel<<<PS_ROWS, 128>>>();

    // Stage 2: cp.async-pipelined fp16 GEMM, k-chunk 64
    stage2_mma_kernel<<<dim3(ND / 128, M2 / 128), 256, SMEM2>>>(b2, out);

    // Length pass-through if the output buffer has room
    if ((long)out_size >= MAIN_OUT + 2 * NB)
        tail_kernel<<<1, 32>>>(slen, tlen, out);
}

// round 12
// speedup vs baseline: 5.1363x; 1.0481x over previous
#include <cuda_runtime.h>
#include <cuda_fp16.h>
#include <math.h>
#include <stdint.h>

// Problem dims
constexpr int NB = 8, NT = 256, NU = 64, ND = 512, NH = 1024;
constexpr int PS_ROWS = NB * NT;              // 2048
constexpr int PT_ROWS = NB * NU;              // 512
constexpr int P_ROWS  = PS_ROWS + PT_ROWS;    // 2560
constexpr int M2      = NB * NT * NU;         // 131072
constexpr long MAIN_OUT = (long)M2 * ND;      // 67,108,864

// Scratch
__device__ float  g_P[(size_t)P_ROWS * NH];   // 10 MB
__device__ __half g_W1h[(size_t)NH * ND];     // W1^T [n][k] fp16 hi
__device__ __half g_W1l[(size_t)NH * ND];     // fp16 lo residual
__device__ __half g_W2h[(size_t)ND * NH];     // W2^T [n][k] fp16
__device__ __half g_H[(size_t)M2 * NH];       // H = fp16(tanh(Ps+Pt)), 268 MB

// ===========================================================================
// Helpers (plain PTX, compute_100-safe)
// ===========================================================================
__device__ __forceinline__ uint32_t smem_u32(const void* p) {
    uint32_t a;
    asm("{ .reg .u64 t; cvta.to.shared.u64 t, %1; cvt.u32.u64 %0, t; }" : "=r"(a) : "l"(p));
    return a;
}

#define LDSM_X4(r, addr) \
    asm volatile("ldmatrix.sync.aligned.m8n8.x4.shared.b16 {%0,%1,%2,%3}, [%4];" \
        : "=r"((r)[0]), "=r"((r)[1]), "=r"((r)[2]), "=r"((r)[3]) : "r"(addr))

__device__ __forceinline__ void mma16816(float* d, const uint32_t* a,
                                         uint32_t b0, uint32_t b1) {
    asm volatile(
        "mma.sync.aligned.m16n8k16.row.col.f32.f16.f16.f32 "
        "{%0,%1,%2,%3}, {%4,%5,%6,%7}, {%8,%9}, {%0,%1,%2,%3};"
        : "+f"(d[0]), "+f"(d[1]), "+f"(d[2]), "+f"(d[3])
        : "r"(a[0]), "r"(a[1]), "r"(a[2]), "r"(a[3]), "r"(b0), "r"(b1));
}

__device__ __forceinline__ void cp_async16(uint32_t dst, const void* src) {
    asm volatile("cp.async.cg.shared.global [%0], [%1], 16;"
        :: "r"(dst), "l"(__cvta_generic_to_global(src)) : "memory");
}
#define CP_COMMIT()  asm volatile("cp.async.commit_group;" ::: "memory")
#define CP_WAIT(n)   asm volatile("cp.async.wait_group %0;" :: "n"(n) : "memory")

// HW tanh (sm_75+): 1 MUFU op, max abs err ~4.9e-4.
__device__ __forceinline__ float hw_tanh(float x) {
    float y;
    asm("tanh.approx.f32 %0, %1;" : "=f"(y) : "f"(x));
    return y;
}

// ===========================================================================
// Weight preconverts (fused single kernel)
//   i < NH*ND      : W1^T hi/lo split
//   i >= NH*ND     : W2^T fp16
// ===========================================================================
constexpr int W1N = NH * ND;                  // 524288
constexpr int W2N = ND * NH;                  // 524288
__global__ __launch_bounds__(256) void wconv_kernel(
    const float* __restrict__ W1, const float* __restrict__ W2)
{
    int i = blockIdx.x * 256 + threadIdx.x;
    if (i < W1N) {                            // [n][k], n<NH, k<ND
        int n = i >> 9;
        int k = i & (ND - 1);
        float v = W1[(size_t)k * NH + n];
        __half h = __float2half_rn(v);
        g_W1h[i] = h;
        g_W1l[i] = __float2half_rn(v - __half2float(h));
    } else {                                  // [n][k], n<ND, k<NH
        int j = i - W1N;
        int n = j >> 10;
        int k = j & (NH - 1);
        g_W2h[j] = __float2half_rn(W2[(size_t)k * ND + n]);
    }
}

// ===========================================================================
// Stage 1 (mma.sync, 3-product fp16 split): P = concat(S,Tgt) @ W1 (+b1 Tgt)
// ===========================================================================
constexpr int RS1     = 80;
constexpr int KCH1    = 32;
constexpr int NCH1    = ND / KCH1;            // 16
constexpr int TILE1   = 128 * RS1;            // 10240
constexpr int BUFSZ1  = 4 * TILE1;            // Ah, Al, Bh, Bl
constexpr int SMEM1   = 2 * BUFSZ1;           // 81920

__global__ void __launch_bounds__(256, 2) stage1_mma_kernel(
    const float* __restrict__ src, const float* __restrict__ tgt,
    const float* __restrict__ b1)
{
    extern __shared__ __align__(16) unsigned char dynsm[];

    const int tid  = threadIdx.x;
    const int lane = tid & 31, wid = tid >> 5;
    const int warpM = wid >> 1, warpN = wid & 1;
    const int nBase = blockIdx.x * 128;
    const int mBase = blockIdx.y * 128;
    const bool isTgt = (mBase >= PS_ROWS);

    const int gr = tid >> 1;
    const int gk = (tid & 1) * 16;
    const float* aRow = (isTgt ? tgt + (size_t)(mBase - PS_ROWS + gr) * ND
                               : src + (size_t)(mBase + gr) * ND) + gk;
    const __half* bhS = g_W1h + (size_t)(nBase + gr) * ND + gk;
    const __half* blS = g_W1l + (size_t)(nBase + gr) * ND + gk;

    const int sel = lane >> 3, l7 = lane & 7;
    const uint32_t aOff = (uint32_t)((warpM * 32 + (sel & 1) * 8 + l7) * RS1 + (sel >> 1) * 16);
    const uint32_t bOff = (uint32_t)((warpN * 64 + ((sel >> 1) & 1) * 8 + l7) * RS1 + (sel & 1) * 16);
    const uint32_t sbase = smem_u32(dynsm);

    float acc[2][8][4];
    #pragma unroll
    for (int mt = 0; mt < 2; ++mt)
        #pragma unroll
        for (int nt = 0; nt < 8; ++nt)
            #pragma unroll
            for (int j = 0; j < 4; ++j) acc[mt][nt][j] = 0.f;

    auto gen = [&](int c, int buf) {
        unsigned char* bp = dynsm + buf * BUFSZ1;
        const float* p = aRow + c * KCH1;
        uint32_t hw[8], lw[8];
        #pragma unroll
        for (int g = 0; g < 4; ++g) {
            float4 p4 = *(const float4*)(p + g * 4);
            __half hx = __float2half_rn(p4.x), hy = __float2half_rn(p4.y);
            __half hz = __float2half_rn(p4.z), hw4 = __float2half_rn(p4.w);
            __half2 h0; h0.x = hx; h0.y = hy;
            __half2 h1; h1.x = hz; h1.y = hw4;
            __half2 l0 = __floats2half2_rn(p4.x - __half2float(hx), p4.y - __half2float(hy));
            __half2 l1 = __floats2half2_rn(p4.z - __half2float(hz), p4.w - __half2float(hw4));
            hw[g * 2 + 0] = *(uint32_t*)&h0; hw[g * 2 + 1] = *(uint32_t*)&h1;
            lw[g * 2 + 0] = *(uint32_t*)&l0; lw[g * 2 + 1] = *(uint32_t*)&l1;
        }
        unsigned char* aH = bp + gr * RS1 + gk * 2;
        unsigned char* aL = aH + TILE1;
        *(uint4*)(aH)      = make_uint4(hw[0], hw[1], hw[2], hw[3]);
        *(uint4*)(aH + 16) = make_uint4(hw[4], hw[5], hw[6], hw[7]);
        *(uint4*)(aL)      = make_uint4(lw[0], lw[1], lw[2], lw[3]);
        *(uint4*)(aL + 16) = make_uint4(lw[4], lw[5], lw[6], lw[7]);

        uint4 h0 = *(const uint4*)(bhS + c * KCH1);
        uint4 h1 = *(const uint4*)(bhS + c * KCH1 + 8);
        uint4 l0 = *(const uint4*)(blS + c * KCH1);
        uint4 l1 = *(const uint4*)(blS + c * KCH1 + 8);
        unsigned char* bH = bp + 2 * TILE1 + gr * RS1 + gk * 2;
        unsigned char* bL = bH + TILE1;
        *(uint4*)(bH)      = h0; *(uint4*)(bH + 16) = h1;
        *(uint4*)(bL)      = l0; *(uint4*)(bL + 16) = l1;
    };

    gen(0, 0);
    __syncthreads();

    for (int c = 0; c < NCH1; ++c) {
        const int buf = c & 1;
        const uint32_t base = sbase + buf * BUFSZ1;

        uint32_t ah[2][2][4], al[2][2][4];
        #pragma unroll
        for (int ks = 0; ks < 2; ++ks) {
            LDSM_X4(ah[ks][0], base + aOff + ks * 32);
            LDSM_X4(ah[ks][1], base + aOff + 16 * RS1 + ks * 32);
            LDSM_X4(al[ks][0], base + TILE1 + aOff + ks * 32);
            LDSM_X4(al[ks][1], base + TILE1 + aOff + 16 * RS1 + ks * 32);
        }
        #pragma unroll
        for (int pass = 0; pass < 3; ++pass) {
            const uint32_t bB = base + (pass == 1 ? 3 : 2) * TILE1 + bOff;
            #pragma unroll
            for (int ks = 0; ks < 2; ++ks) {
                uint32_t bf[4][4];
                #pragma unroll
                for (int g = 0; g < 4; ++g)
                    LDSM_X4(bf[g], bB + g * 16 * RS1 + ks * 32);
                #pragma unroll
                for (int mt = 0; mt < 2; ++mt)
                    #pragma unroll
                    for (int nt = 0; nt < 8; ++nt)
                        mma16816(acc[mt][nt],
                                 (pass == 2 ? al[ks][mt] : ah[ks][mt]),
                                 bf[nt >> 1][(nt & 1) * 2 + 0],
                                 bf[nt >> 1][(nt & 1) * 2 + 1]);
            }
        }
        if (c + 1 < NCH1) gen(c + 1, buf ^ 1);
        __syncthreads();
    }

    const int colOff = (lane & 3) * 2;
    const int rowOff = lane >> 2;
    #pragma unroll
    for (int mt = 0; mt < 2; ++mt) {
        const int r0 = mBase + warpM * 32 + mt * 16 + rowOff;
        float* row0 = g_P + (size_t)r0 * NH + nBase + warpN * 64 + colOff;
        float* row1 = row0 + (size_t)8 * NH;
        #pragma unroll
        for (int nt = 0; nt < 8; ++nt) {
            const int col = nBase + warpN * 64 + nt * 8 + colOff;
            const float bx = isTgt ? __ldg(b1 + col)     : 0.f;
            const float by = isTgt ? __ldg(b1 + col + 1) : 0.f;
            *(float2*)(row0 + nt * 8) = make_float2(acc[mt][nt][0] + bx, acc[mt][nt][1] + by);
            *(float2*)(row1 + nt * 8) = make_float2(acc[mt][nt][2] + bx, acc[mt][nt][3] + by);
        }
    }
}

// ===========================================================================
// Stage 1.5: H[m][k] = fp16(tanh.approx(Ps[b,t][k] + Pt[b,u][k]))
//   1 MUFU per element (was 2) — MUFU pressure halved.
// ===========================================================================
__global__ __launch_bounds__(128) void h_kernel()
{
    const int bt = blockIdx.x;                // b*NT + t
    const int b  = bt >> 8;
    const int k0 = threadIdx.x * 8;

    const float* ps = g_P + (size_t)bt * NH + k0;
    const float4 p0 = *(const float4*)(ps);
    const float4 p1 = *(const float4*)(ps + 4);

    const float* ptB = g_P + (size_t)(PS_ROWS + b * NU) * NH + k0;
    __half* hout = g_H + (size_t)bt * NU * NH + k0;

    for (int u = 0; u < NU; ++u) {
        const float* q = ptB + (size_t)u * NH;
        float4 q0 = *(const float4*)(q);
        float4 q1 = *(const float4*)(q + 4);
        __half2 h0 = __floats2half2_rn(hw_tanh(p0.x + q0.x), hw_tanh(p0.y + q0.y));
        __half2 h1 = __floats2half2_rn(hw_tanh(p0.z + q0.z), hw_tanh(p0.w + q0.w));
        __half2 h2 = __floats2half2_rn(hw_tanh(p1.x + q1.x), hw_tanh(p1.y + q1.y));
        __half2 h3 = __floats2half2_rn(hw_tanh(p1.z + q1.z), hw_tanh(p1.w + q1.w));
        *(uint4*)(hout + (size_t)u * NH) =
            make_uint4(*(uint32_t*)&h0, *(uint32_t*)&h1, *(uint32_t*)&h2, *(uint32_t*)&h3);
    }
}

// ===========================================================================
// Stage 2: out = H @ W2^T + b2 — fp16 GEMM, k-chunk 64, 3-stage cp.async.
// ===========================================================================
constexpr int RS2  = 144;
constexpr int KCH2 = 64;
constexpr int NCH2 = NH / KCH2;               // 16
constexpr int TILE2  = 128 * RS2;             // 18432
constexpr int BUFSZ2 = 2 * TILE2;
constexpr int NSTAGE = 3;
constexpr int SMEM2  = NSTAGE * BUFSZ2;       // 110592

__global__ void __launch_bounds__(256, 2) stage2_mma_kernel(
    const float* __restrict__ b2, float* __restrict__ out)
{
    extern __shared__ __align__(16) unsigned char dynsm[];

    const int tid  = threadIdx.x;
    const int lane = tid & 31, wid = tid >> 5;
    const int warpM = wid >> 1, warpN = wid & 1;
    const int nBase = blockIdx.x * 128;
    const int mBase = blockIdx.y * 128;

    const int gr = tid >> 1;
    const int gk = (tid & 1) * 32;
    const __half* aS0 = g_H   + (size_t)(mBase + gr) * NH + gk;
    const __half* bS0 = g_W2h + (size_t)(nBase + gr) * NH + gk;
    const uint32_t dOffA = (uint32_t)(gr * RS2 + gk * 2);
    const uint32_t dOffB = (uint32_t)(TILE2 + gr * RS2 + gk * 2);

    const int sel = lane >> 3, l7 = lane & 7;
    const uint32_t aOff = (uint32_t)((warpM * 32 + (sel & 1) * 8 + l7) * RS2 + (sel >> 1) * 16);
    const uint32_t bOff = (uint32_t)((warpN * 64 + ((sel >> 1) & 1) * 8 + l7) * RS2 + (sel & 1) * 16);
    const uint32_t sbase = smem_u32(dynsm);

    float acc[2][8][4];
    #pragma unroll
    for (int mt = 0; mt < 2; ++mt)
        #pragma unroll
        for (int nt = 0; nt < 8; ++nt)
            #pragma unroll
            for (int j = 0; j < 4; ++j) acc[mt][nt][j] = 0.f;

    auto issue_cp = [&](int c, int stage) {
        const uint32_t base = sbase + stage * BUFSZ2;
        const __half* aS = aS0 + c * KCH2;
        const __half* bS = bS0 + c * KCH2;
        #pragma unroll
        for (int g = 0; g < 4; ++g) {
            cp_async16(base + dOffA + g * 16, aS + g * 8);
            cp_async16(base + dOffB + g * 16, bS + g * 8);
        }
        CP_COMMIT();
    };

    issue_cp(0, 0);
    issue_cp(1, 1);

    int rd = 0, wr = 2;
    for (int c = 0; c < NCH2; ++c) {
        if (c == NCH2 - 1) { CP_WAIT(0); } else { CP_WAIT(1); }
        __syncthreads();

        const uint32_t base = sbase + rd * BUFSZ2;
        const uint32_t aB = base + aOff;
        const uint32_t bB = base + TILE2 + bOff;

        #pragma unroll
        for (int ks = 0; ks < 4; ++ks) {
            uint32_t a[2][4];
            LDSM_X4(a[0], aB + ks * 32);
            LDSM_X4(a[1], aB + 16 * RS2 + ks * 32);
            uint32_t bf[4][4];
            #pragma unroll
            for (int g = 0; g < 4; ++g)
                LDSM_X4(bf[g], bB + g * 16 * RS2 + ks * 32);
            #pragma unroll
            for (int mt = 0; mt < 2; ++mt)
                #pragma unroll
                for (int nt = 0; nt < 8; ++nt)
                    mma16816(acc[mt][nt], a[mt],
                             bf[nt >> 1][(nt & 1) * 2 + 0],
                             bf[nt >> 1][(nt & 1) * 2 + 1]);
        }

        if (c + 2 < NCH2) issue_cp(c + 2, wr);
        rd = (rd == 2) ? 0 : rd + 1;
        wr = (wr == 2) ? 0 : wr + 1;
    }

    const int colOff = (lane & 3) * 2;
    const int rowOff = lane >> 2;
    #pragma unroll
    for (int mt = 0; mt < 2; ++mt) {
        const int r0 = mBase + warpM * 32 + mt * 16 + rowOff;
        float* row0 = out + (size_t)r0 * ND + nBase + warpN * 64 + colOff;
        float* row1 = row0 + (size_t)8 * ND;
        #pragma unroll
        for (int nt = 0; nt < 8; ++nt) {
            const float bx = __ldg(b2 + nBase + warpN * 64 + nt * 8 + colOff);
            const float by = __ldg(b2 + nBase + warpN * 64 + nt * 8 + colOff + 1);
            *(float2*)(row0 + nt * 8) = make_float2(acc[mt][nt][0] + bx, acc[mt][nt][1] + by);
            *(float2*)(row1 + nt * 8) = make_float2(acc[mt][nt][2] + bx, acc[mt][nt][3] + by);
        }
    }
}

// ---------------------------------------------------------------------------
// Length pass-through tail
// ---------------------------------------------------------------------------
__global__ void tail_kernel(const int* __restrict__ sl, const int* __restrict__ tl,
                            float* __restrict__ out)
{
    const int i = threadIdx.x;
    if (i < NB)           out[MAIN_OUT + i] = (float)sl[i];
    else if (i < 2 * NB)  out[MAIN_OUT + i] = (float)tl[i - NB];
}

extern "C" void kernel_launch(void* const* d_in, const int* in_sizes, int n_in,
                              void* d_out, int out_size)
{
    const float* src  = (const float*)d_in[0];
    const int*   slen = (const int*)  d_in[1];
    const float* tgt  = (const float*)d_in[2];
    const int*   tlen = (const int*)  d_in[3];
    const float* W1   = (const float*)d_in[4];
    const float* b1   = (const float*)d_in[5];
    const float* W2   = (const float*)d_in[6];
    const float* b2   = (const float*)d_in[7];
    float* out = (float*)d_out;

    // Opt-in to >48KB dynamic smem (host-side, capture-safe).
    cudaFuncSetAttribute(stage1_mma_kernel,
                         cudaFuncAttributeMaxDynamicSharedMemorySize, SMEM1);
    cudaFuncSetAttribute(stage2_mma_kernel,
                         cudaFuncAttributeMaxDynamicSharedMemorySize, SMEM2);

    // Fused weight preconverts
    wconv_kernel<<<(W1N + W2N) / 256, 256>>>(W1, W2);

    // Stage 1: P = [S; Tgt] @ W1 (+ b1 on Tgt rows)
    stage1_mma_kernel<<<dim3(NH / 128, P_ROWS / 128), 256, SMEM1>>>(src, tgt, b1);

    // Stage 1.5: H = fp16(tanh.approx(Ps + Pt))
    h_kernel<<<PS_ROWS, 128>>>();

    // Stage 2: cp.async-pipelined fp16 GEMM
    stage2_mma_kernel<<<dim3(ND / 128, M2 / 128), 256, SMEM2>>>(b2, out);

    // Length pass-through if the output buffer has room
    if ((long)out_size >= MAIN_OUT + 2 * NB)
        tail_kernel<<<1, 32>>>(slen, tlen, out);
}

// round 13
// speedup vs baseline: 5.5619x; 1.0829x over previous
#include <cuda_runtime.h>
#include <cuda_fp16.h>
#include <math.h>
#include <stdint.h>

// Problem dims
constexpr int NB = 8, NT = 256, NU = 64, ND = 512, NH = 1024;
constexpr int PS_ROWS = NB * NT;              // 2048
constexpr int PT_ROWS = NB * NU;              // 512
constexpr int P_ROWS  = PS_ROWS + PT_ROWS;    // 2560
constexpr int M2      = NB * NT * NU;         // 131072
constexpr long MAIN_OUT = (long)M2 * ND;      // 67,108,864

// Scratch
__device__ float  g_P[(size_t)P_ROWS * NH];   // 10 MB
__device__ __half g_W1h[(size_t)NH * ND];     // W1^T [n][k] fp16 hi
__device__ __half g_W1l[(size_t)NH * ND];     // fp16 lo residual
__device__ __half g_W2h[(size_t)ND * NH];     // W2^T [n][k] fp16
__device__ __half g_H[(size_t)M2 * NH];       // H = fp16(tanh(Ps+Pt)), 268 MB

// ===========================================================================
// Helpers (plain PTX, compute_100-safe)
// ===========================================================================
__device__ __forceinline__ uint32_t smem_u32(const void* p) {
    uint32_t a;
    asm("{ .reg .u64 t; cvta.to.shared.u64 t, %1; cvt.u32.u64 %0, t; }" : "=r"(a) : "l"(p));
    return a;
}

#define LDSM_X4(r, addr) \
    asm volatile("ldmatrix.sync.aligned.m8n8.x4.shared.b16 {%0,%1,%2,%3}, [%4];" \
        : "=r"((r)[0]), "=r"((r)[1]), "=r"((r)[2]), "=r"((r)[3]) : "r"(addr))

__device__ __forceinline__ void mma16816(float* d, const uint32_t* a,
                                         uint32_t b0, uint32_t b1) {
    asm volatile(
        "mma.sync.aligned.m16n8k16.row.col.f32.f16.f16.f32 "
        "{%0,%1,%2,%3}, {%4,%5,%6,%7}, {%8,%9}, {%0,%1,%2,%3};"
        : "+f"(d[0]), "+f"(d[1]), "+f"(d[2]), "+f"(d[3])
        : "r"(a[0]), "r"(a[1]), "r"(a[2]), "r"(a[3]), "r"(b0), "r"(b1));
}

__device__ __forceinline__ void cp_async16(uint32_t dst, const void* src) {
    asm volatile("cp.async.cg.shared.global [%0], [%1], 16;"
        :: "r"(dst), "l"(__cvta_generic_to_global(src)) : "memory");
}
#define CP_COMMIT()  asm volatile("cp.async.commit_group;" ::: "memory")
#define CP_WAIT(n)   asm volatile("cp.async.wait_group %0;" :: "n"(n) : "memory")

// HW tanh (sm_75+): 1 MUFU op; error below fp16-H quantization (measured R12).
__device__ __forceinline__ float hw_tanh(float x) {
    float y;
    asm("tanh.approx.f32 %0, %1;" : "=f"(y) : "f"(x));
    return y;
}

// ===========================================================================
// Weight preconverts (fused single kernel)
// ===========================================================================
constexpr int W1N = NH * ND;                  // 524288
constexpr int W2N = ND * NH;                  // 524288
__global__ __launch_bounds__(256) void wconv_kernel(
    const float* __restrict__ W1, const float* __restrict__ W2)
{
    int i = blockIdx.x * 256 + threadIdx.x;
    if (i < W1N) {                            // [n][k], n<NH, k<ND
        int n = i >> 9;
        int k = i & (ND - 1);
        float v = W1[(size_t)k * NH + n];
        __half h = __float2half_rn(v);
        g_W1h[i] = h;
        g_W1l[i] = __float2half_rn(v - __half2float(h));
    } else {                                  // [n][k], n<ND, k<NH
        int j = i - W1N;
        int n = j >> 10;
        int k = j & (NH - 1);
        g_W2h[j] = __float2half_rn(W2[(size_t)k * ND + n]);
    }
}

// ===========================================================================
// Stage 1 (mma.sync, 3-product fp16 split): P = concat(S,Tgt) @ W1 (+b1 Tgt)
// ===========================================================================
constexpr int RS1     = 80;
constexpr int KCH1    = 32;
constexpr int NCH1    = ND / KCH1;            // 16
constexpr int TILE1   = 128 * RS1;            // 10240
constexpr int BUFSZ1  = 4 * TILE1;            // Ah, Al, Bh, Bl
constexpr int SMEM1   = 2 * BUFSZ1;           // 81920

__global__ void __launch_bounds__(256, 2) stage1_mma_kernel(
    const float* __restrict__ src, const float* __restrict__ tgt,
    const float* __restrict__ b1)
{
    extern __shared__ __align__(16) unsigned char dynsm[];

    const int tid  = threadIdx.x;
    const int lane = tid & 31, wid = tid >> 5;
    const int warpM = wid >> 1, warpN = wid & 1;
    const int nBase = blockIdx.x * 128;
    const int mBase = blockIdx.y * 128;
    const bool isTgt = (mBase >= PS_ROWS);

    const int gr = tid >> 1;
    const int gk = (tid & 1) * 16;
    const float* aRow = (isTgt ? tgt + (size_t)(mBase - PS_ROWS + gr) * ND
                               : src + (size_t)(mBase + gr) * ND) + gk;
    const __half* bhS = g_W1h + (size_t)(nBase + gr) * ND + gk;
    const __half* blS = g_W1l + (size_t)(nBase + gr) * ND + gk;

    const int sel = lane >> 3, l7 = lane & 7;
    const uint32_t aOff = (uint32_t)((warpM * 32 + (sel & 1) * 8 + l7) * RS1 + (sel >> 1) * 16);
    const uint32_t bOff = (uint32_t)((warpN * 64 + ((sel >> 1) & 1) * 8 + l7) * RS1 + (sel & 1) * 16);
    const uint32_t sbase = smem_u32(dynsm);

    float acc[2][8][4];
    #pragma unroll
    for (int mt = 0; mt < 2; ++mt)
        #pragma unroll
        for (int nt = 0; nt < 8; ++nt)
            #pragma unroll
            for (int j = 0; j < 4; ++j) acc[mt][nt][j] = 0.f;

    auto gen = [&](int c, int buf) {
        unsigned char* bp = dynsm + buf * BUFSZ1;
        const float* p = aRow + c * KCH1;
        uint32_t hw[8], lw[8];
        #pragma unroll
        for (int g = 0; g < 4; ++g) {
            float4 p4 = *(const float4*)(p + g * 4);
            __half hx = __float2half_rn(p4.x), hy = __float2half_rn(p4.y);
            __half hz = __float2half_rn(p4.z), hw4 = __float2half_rn(p4.w);
            __half2 h0; h0.x = hx; h0.y = hy;
            __half2 h1; h1.x = hz; h1.y = hw4;
            __half2 l0 = __floats2half2_rn(p4.x - __half2float(hx), p4.y - __half2float(hy));
            __half2 l1 = __floats2half2_rn(p4.z - __half2float(hz), p4.w - __half2float(hw4));
            hw[g * 2 + 0] = *(uint32_t*)&h0; hw[g * 2 + 1] = *(uint32_t*)&h1;
            lw[g * 2 + 0] = *(uint32_t*)&l0; lw[g * 2 + 1] = *(uint32_t*)&l1;
        }
        unsigned char* aH = bp + gr * RS1 + gk * 2;
        unsigned char* aL = aH + TILE1;
        *(uint4*)(aH)      = make_uint4(hw[0], hw[1], hw[2], hw[3]);
        *(uint4*)(aH + 16) = make_uint4(hw[4], hw[5], hw[6], hw[7]);
        *(uint4*)(aL)      = make_uint4(lw[0], lw[1], lw[2], lw[3]);
        *(uint4*)(aL + 16) = make_uint4(lw[4], lw[5], lw[6], lw[7]);

        uint4 h0 = *(const uint4*)(bhS + c * KCH1);
        uint4 h1 = *(const uint4*)(bhS + c * KCH1 + 8);
        uint4 l0 = *(const uint4*)(blS + c * KCH1);
        uint4 l1 = *(const uint4*)(blS + c * KCH1 + 8);
        unsigned char* bH = bp + 2 * TILE1 + gr * RS1 + gk * 2;
        unsigned char* bL = bH + TILE1;
        *(uint4*)(bH)      = h0; *(uint4*)(bH + 16) = h1;
        *(uint4*)(bL)      = l0; *(uint4*)(bL + 16) = l1;
    };

    gen(0, 0);
    __syncthreads();

    for (int c = 0; c < NCH1; ++c) {
        const int buf = c & 1;
        const uint32_t base = sbase + buf * BUFSZ1;

        uint32_t ah[2][2][4], al[2][2][4];
        #pragma unroll
        for (int ks = 0; ks < 2; ++ks) {
            LDSM_X4(ah[ks][0], base + aOff + ks * 32);
            LDSM_X4(ah[ks][1], base + aOff + 16 * RS1 + ks * 32);
            LDSM_X4(al[ks][0], base + TILE1 + aOff + ks * 32);
            LDSM_X4(al[ks][1], base + TILE1 + aOff + 16 * RS1 + ks * 32);
        }
        #pragma unroll
        for (int pass = 0; pass < 3; ++pass) {
            const uint32_t bB = base + (pass == 1 ? 3 : 2) * TILE1 + bOff;
            #pragma unroll
            for (int ks = 0; ks < 2; ++ks) {
                uint32_t bf[4][4];
                #pragma unroll
                for (int g = 0; g < 4; ++g)
                    LDSM_X4(bf[g], bB + g * 16 * RS1 + ks * 32);
                #pragma unroll
                for (int mt = 0; mt < 2; ++mt)
                    #pragma unroll
                    for (int nt = 0; nt < 8; ++nt)
                        mma16816(acc[mt][nt],
                                 (pass == 2 ? al[ks][mt] : ah[ks][mt]),
                                 bf[nt >> 1][(nt & 1) * 2 + 0],
                                 bf[nt >> 1][(nt & 1) * 2 + 1]);
            }
        }
        if (c + 1 < NCH1) gen(c + 1, buf ^ 1);
        __syncthreads();
    }

    const int colOff = (lane & 3) * 2;
    const int rowOff = lane >> 2;
    #pragma unroll
    for (int mt = 0; mt < 2; ++mt) {
        const int r0 = mBase + warpM * 32 + mt * 16 + rowOff;
        float* row0 = g_P + (size_t)r0 * NH + nBase + warpN * 64 + colOff;
        float* row1 = row0 + (size_t)8 * NH;
        #pragma unroll
        for (int nt = 0; nt < 8; ++nt) {
            const int col = nBase + warpN * 64 + nt * 8 + colOff;
            const float bx = isTgt ? __ldg(b1 + col)     : 0.f;
            const float by = isTgt ? __ldg(b1 + col + 1) : 0.f;
            *(float2*)(row0 + nt * 8) = make_float2(acc[mt][nt][0] + bx, acc[mt][nt][1] + by);
            *(float2*)(row1 + nt * 8) = make_float2(acc[mt][nt][2] + bx, acc[mt][nt][3] + by);
        }
    }
}

// ===========================================================================
// Stage 1.5: H[m][k] = fp16(tanh.approx(Ps[b,t][k] + Pt[b,u][k]))
// ===========================================================================
__global__ __launch_bounds__(128) void h_kernel()
{
    const int bt = blockIdx.x;                // b*NT + t
    const int b  = bt >> 8;
    const int k0 = threadIdx.x * 8;

    const float* ps = g_P + (size_t)bt * NH + k0;
    const float4 p0 = *(const float4*)(ps);
    const float4 p1 = *(const float4*)(ps + 4);

    const float* ptB = g_P + (size_t)(PS_ROWS + b * NU) * NH + k0;
    __half* hout = g_H + (size_t)bt * NU * NH + k0;

    for (int u = 0; u < NU; ++u) {
        const float* q = ptB + (size_t)u * NH;
        float4 q0 = *(const float4*)(q);
        float4 q1 = *(const float4*)(q + 4);
        __half2 h0 = __floats2half2_rn(hw_tanh(p0.x + q0.x), hw_tanh(p0.y + q0.y));
        __half2 h1 = __floats2half2_rn(hw_tanh(p0.z + q0.z), hw_tanh(p0.w + q0.w));
        __half2 h2 = __floats2half2_rn(hw_tanh(p1.x + q1.x), hw_tanh(p1.y + q1.y));
        __half2 h3 = __floats2half2_rn(hw_tanh(p1.z + q1.z), hw_tanh(p1.w + q1.w));
        *(uint4*)(hout + (size_t)u * NH) =
            make_uint4(*(uint32_t*)&h0, *(uint32_t*)&h1, *(uint32_t*)&h2, *(uint32_t*)&h3);
    }
}

// ===========================================================================
// Stage 2: out = H @ W2^T + b2 — fp16 GEMM, R10-exact config:
//   k-chunk 32, RS 80, 3-stage cp.async. (KCH=64/RS=144 measured slower.)
// ===========================================================================
constexpr int RS2  = 80;                      // bytes per 32-fp16 row (padded)
constexpr int KCH2 = 32;
constexpr int NCH2 = NH / KCH2;               // 32
constexpr int TILE2  = 128 * RS2;             // 10240
constexpr int BUFSZ2 = 2 * TILE2;             // A, B
constexpr int NSTAGE = 3;
constexpr int SMEM2  = NSTAGE * BUFSZ2;       // 61440

__global__ void __launch_bounds__(256, 2) stage2_mma_kernel(
    const float* __restrict__ b2, float* __restrict__ out)
{
    extern __shared__ __align__(16) unsigned char dynsm[];

    const int tid  = threadIdx.x;
    const int lane = tid & 31, wid = tid >> 5;
    const int warpM = wid >> 1, warpN = wid & 1;
    const int nBase = blockIdx.x * 128;
    const int mBase = blockIdx.y * 128;

    // copy mapping: row = tid>>1, k-half = (tid&1)*16
    const int gr = tid >> 1;
    const int gk = (tid & 1) * 16;
    const __half* aS0 = g_H   + (size_t)(mBase + gr) * NH + gk;
    const __half* bS0 = g_W2h + (size_t)(nBase + gr) * NH + gk;
    const uint32_t dOffA = (uint32_t)(gr * RS2 + gk * 2);
    const uint32_t dOffB = (uint32_t)(TILE2 + gr * RS2 + gk * 2);

    const int sel = lane >> 3, l7 = lane & 7;
    const uint32_t aOff = (uint32_t)((warpM * 32 + (sel & 1) * 8 + l7) * RS2 + (sel >> 1) * 16);
    const uint32_t bOff = (uint32_t)((warpN * 64 + ((sel >> 1) & 1) * 8 + l7) * RS2 + (sel & 1) * 16);
    const uint32_t sbase = smem_u32(dynsm);

    float acc[2][8][4];
    #pragma unroll
    for (int mt = 0; mt < 2; ++mt)
        #pragma unroll
        for (int nt = 0; nt < 8; ++nt)
            #pragma unroll
            for (int j = 0; j < 4; ++j) acc[mt][nt][j] = 0.f;

    auto issue_cp = [&](int c, int stage) {
        const uint32_t base = sbase + stage * BUFSZ2;
        const __half* aS = aS0 + c * KCH2;
        const __half* bS = bS0 + c * KCH2;
        cp_async16(base + dOffA,      aS);
        cp_async16(base + dOffA + 16, aS + 8);
        cp_async16(base + dOffB,      bS);
        cp_async16(base + dOffB + 16, bS + 8);
        CP_COMMIT();
    };

    issue_cp(0, 0);
    issue_cp(1, 1);

    int rd = 0, wr = 2;
    for (int c = 0; c < NCH2; ++c) {
        if (c == NCH2 - 1) { CP_WAIT(0); } else { CP_WAIT(1); }
        __syncthreads();

        const uint32_t base = sbase + rd * BUFSZ2;
        const uint32_t aB = base + aOff;
        const uint32_t bB = base + TILE2 + bOff;

        #pragma unroll
        for (int ks = 0; ks < 2; ++ks) {
            uint32_t a[2][4];
            LDSM_X4(a[0], aB + ks * 32);
            LDSM_X4(a[1], aB + 16 * RS2 + ks * 32);
            uint32_t bf[4][4];
            #pragma unroll
            for (int g = 0; g < 4; ++g)
                LDSM_X4(bf[g], bB + g * 16 * RS2 + ks * 32);
            #pragma unroll
            for (int mt = 0; mt < 2; ++mt)
                #pragma unroll
                for (int nt = 0; nt < 8; ++nt)
                    mma16816(acc[mt][nt], a[mt],
                             bf[nt >> 1][(nt & 1) * 2 + 0],
                             bf[nt >> 1][(nt & 1) * 2 + 1]);
        }

        if (c + 2 < NCH2) issue_cp(c + 2, wr);
        rd = (rd == 2) ? 0 : rd + 1;
        wr = (wr == 2) ? 0 : wr + 1;
    }

    // Epilogue: + b2, direct stores
    const int colOff = (lane & 3) * 2;
    const int rowOff = lane >> 2;
    #pragma unroll
    for (int mt = 0; mt < 2; ++mt) {
        const int r0 = mBase + warpM * 32 + mt * 16 + rowOff;
        float* row0 = out + (size_t)r0 * ND + nBase + warpN * 64 + colOff;
        float* row1 = row0 + (size_t)8 * ND;
        #pragma unroll
        for (int nt = 0; nt < 8; ++nt) {
            const float bx = __ldg(b2 + nBase + warpN * 64 + nt * 8 + colOff);
            const float by = __ldg(b2 + nBase + warpN * 64 + nt * 8 + colOff + 1);
            *(float2*)(row0 + nt * 8) = make_float2(acc[mt][nt][0] + bx, acc[mt][nt][1] + by);
            *(float2*)(row1 + nt * 8) = make_float2(acc[mt][nt][2] + bx, acc[mt][nt][3] + by);
        }
    }
}

// ---------------------------------------------------------------------------
// Length pass-through tail
// ---------------------------------------------------------------------------
__global__ void tail_kernel(const int* __restrict__ sl, const int* __restrict__ tl,
                            float* __restrict__ out)
{
    const int i = threadIdx.x;
    if (i < NB)           out[MAIN_OUT + i] = (float)sl[i];
    else if (i < 2 * NB)  out[MAIN_OUT + i] = (float)tl[i - NB];
}

extern "C" void kernel_launch(void* const* d_in, const int* in_sizes, int n_in,
                              void* d_out, int out_size)
{
    const float* src  = (const float*)d_in[0];
    const int*   slen = (const int*)  d_in[1];
    const float* tgt  = (const float*)d_in[2];
    const int*   tlen = (const int*)  d_in[3];
    const float* W1   = (const float*)d_in[4];
    const float* b1   = (const float*)d_in[5];
    const float* W2   = (const float*)d_in[6];
    const float* b2   = (const float*)d_in[7];
    float* out = (float*)d_out;

    // Opt-in to >48KB dynamic smem (host-side, capture-safe).
    cudaFuncSetAttribute(stage1_mma_kernel,
                         cudaFuncAttributeMaxDynamicSharedMemorySize, SMEM1);
    cudaFuncSetAttribute(stage2_mma_kernel,
                         cudaFuncAttributeMaxDynamicSharedMemorySize, SMEM2);

    // Fused weight preconverts
    wconv_kernel<<<(W1N + W2N) / 256, 256>>>(W1, W2);

    // Stage 1: P = [S; Tgt] @ W1 (+ b1 on Tgt rows)
    stage1_mma_kernel<<<dim3(NH / 128, P_ROWS / 128), 256, SMEM1>>>(src, tgt, b1);

    // Stage 1.5: H = fp16(tanh.approx(Ps + Pt))
    h_kernel<<<PS_ROWS, 128>>>();

    // Stage 2: cp.async-pipelined fp16 GEMM (R10-exact config)
    stage2_mma_kernel<<<dim3(ND / 128, M2 / 128), 256, SMEM2>>>(b2, out);

    // Length pass-through if the output buffer has room
    if ((long)out_size >= MAIN_OUT + 2 * NB)
        tail_kernel<<<1, 32>>>(slen, tlen, out);
}